// round 4
// baseline (speedup 1.0000x reference)
#include <cuda_runtime.h>
#include <cuda_bf16.h>
#include <math.h>

// Problem constants
#define NND 50000
#define FF  256
#define HH  128
#define EE  800000
#define BB  64
#define TT  50

// ---------------- device scratch ----------------
__device__ float g_reduced[NND * HH];
__device__ float g_agg[NND * HH];
__device__ float g_s[NND * HH];
__device__ float g_invdeg[NND];
__device__ int   g_deg[NND];
__device__ float g_ts[BB * TT * HH];
__device__ float g_gates[BB * TT * 4 * HH];
__device__ float g_h1[BB * TT * HH];
__device__ float g_h2[BB * TT * HH];
__device__ float g_qkv[BB * TT * 3 * HH];
__device__ float g_olast[BB * HH];
__device__ float g_bias0[4 * HH];
__device__ float g_bias1[4 * HH];

__device__ __forceinline__ float sigf(float x) { return 1.0f / (1.0f + __expf(-x)); }

// ---------------- degree kernels ----------------
__global__ __launch_bounds__(256) void deg_kernel(const int* __restrict__ dst, int* __restrict__ deg, int E) {
    int i = blockIdx.x * blockDim.x + threadIdx.x;
    if (i < E) atomicAdd(&deg[dst[i]], 1);
}

__global__ __launch_bounds__(256) void invdeg_kernel(const int* __restrict__ deg, float* __restrict__ inv, int n) {
    int i = blockIdx.x * blockDim.x + threadIdx.x;
    if (i < n) inv[i] = 1.0f / (float)max(deg[i], 1);
}

// ---------------- scatter-add (one warp per edge, v4 reductions) ----------------
__global__ __launch_bounds__(256) void scatter_add_kernel(const float* __restrict__ feat,
                                   const int* __restrict__ src,
                                   const int* __restrict__ dst,
                                   float* __restrict__ agg, int E) {
    int idx = blockIdx.x * blockDim.x + threadIdx.x;
    int e = idx >> 5;
    if (e >= E) return;
    int lane = idx & 31;
    int s = __ldg(src + e);
    int d = __ldg(dst + e);
    float4 v = *(const float4*)(feat + (size_t)s * HH + lane * 4);
    float* p = agg + (size_t)d * HH + lane * 4;
    asm volatile("red.global.add.v4.f32 [%0], {%1,%2,%3,%4};"
                 :: "l"(p), "f"(v.x), "f"(v.y), "f"(v.z), "f"(v.w) : "memory");
}

// ---------------- 128x128-tile NT GEMM: C = A1@B1^T (+ A2@B2^T) + bias, optional relu ----
// A1: M x Ksplit (rows optionally scaled by rowscale[m]), B1: N x Ksplit
// A2: M x (Ktot-Ksplit),                                  B2: N x (Ktot-Ksplit)
// Requirements: Ktot, Ksplit multiples of 16; N multiple of 128.
__global__ __launch_bounds__(256) void gemm_nt_kernel(
                               const float* __restrict__ A1, const float* __restrict__ B1,
                               const float* __restrict__ A2, const float* __restrict__ B2,
                               const float* __restrict__ rowscale,
                               const float* __restrict__ bias,
                               float* __restrict__ C,
                               int M, int N, int Ktot, int Ksplit, int relu) {
    __shared__ float As[2][16][132];
    __shared__ float Bs[2][16][132];
    const int tid = threadIdx.x;            // 256 threads
    const int m0  = blockIdx.x * 128;
    const int n0  = blockIdx.y * 128;
    const int tx  = tid & 15;               // n subtile
    const int ty  = tid >> 4;               // m subtile
    const bool haveScale = (rowscale != nullptr);

    // global-load indexing: 512 float4 per tile (128 rows x 4 float4), 2 per thread
    const int rowA0 = tid >> 2,      c4A0 = tid & 3;
    const int rowA1 = (tid + 256) >> 2, c4A1 = (tid + 256) & 3;

    float acc[8][8];
#pragma unroll
    for (int i = 0; i < 8; i++)
#pragma unroll
        for (int j = 0; j < 8; j++) acc[i][j] = 0.0f;

    const int numTiles = Ktot >> 4;

    // tile loader into registers
    auto loadTile = [&](int kt, float4& ra0, float4& ra1, float4& rb0, float4& rb1) {
        int kbase = kt << 4;
        // first fragment
        {
            int kg = kbase + (c4A0 << 2);
            const float* A; const float* Bm; int lda, koff; bool sc;
            if (kg < Ksplit) { A = A1; Bm = B1; lda = Ksplit;        koff = kg;          sc = haveScale; }
            else             { A = A2; Bm = B2; lda = Ktot - Ksplit; koff = kg - Ksplit; sc = false; }
            int m = m0 + rowA0;
            ra0 = make_float4(0.f, 0.f, 0.f, 0.f);
            if (m < M) {
                ra0 = *(const float4*)(A + (size_t)m * lda + koff);
                if (sc) { float s = rowscale[m]; ra0.x *= s; ra0.y *= s; ra0.z *= s; ra0.w *= s; }
            }
            int n = n0 + rowA0;
            rb0 = make_float4(0.f, 0.f, 0.f, 0.f);
            if (n < N) rb0 = *(const float4*)(Bm + (size_t)n * lda + koff);
        }
        // second fragment
        {
            int kg = kbase + (c4A1 << 2);
            const float* A; const float* Bm; int lda, koff; bool sc;
            if (kg < Ksplit) { A = A1; Bm = B1; lda = Ksplit;        koff = kg;          sc = haveScale; }
            else             { A = A2; Bm = B2; lda = Ktot - Ksplit; koff = kg - Ksplit; sc = false; }
            int m = m0 + rowA1;
            ra1 = make_float4(0.f, 0.f, 0.f, 0.f);
            if (m < M) {
                ra1 = *(const float4*)(A + (size_t)m * lda + koff);
                if (sc) { float s = rowscale[m]; ra1.x *= s; ra1.y *= s; ra1.z *= s; ra1.w *= s; }
            }
            int n = n0 + rowA1;
            rb1 = make_float4(0.f, 0.f, 0.f, 0.f);
            if (n < N) rb1 = *(const float4*)(Bm + (size_t)n * lda + koff);
        }
    };

    auto storeTile = [&](int buf, const float4& ra0, const float4& ra1,
                         const float4& rb0, const float4& rb1) {
        int kc0 = c4A0 << 2;
        As[buf][kc0 + 0][rowA0] = ra0.x; As[buf][kc0 + 1][rowA0] = ra0.y;
        As[buf][kc0 + 2][rowA0] = ra0.z; As[buf][kc0 + 3][rowA0] = ra0.w;
        Bs[buf][kc0 + 0][rowA0] = rb0.x; Bs[buf][kc0 + 1][rowA0] = rb0.y;
        Bs[buf][kc0 + 2][rowA0] = rb0.z; Bs[buf][kc0 + 3][rowA0] = rb0.w;
        int kc1 = c4A1 << 2;
        As[buf][kc1 + 0][rowA1] = ra1.x; As[buf][kc1 + 1][rowA1] = ra1.y;
        As[buf][kc1 + 2][rowA1] = ra1.z; As[buf][kc1 + 3][rowA1] = ra1.w;
        Bs[buf][kc1 + 0][rowA1] = rb1.x; Bs[buf][kc1 + 1][rowA1] = rb1.y;
        Bs[buf][kc1 + 2][rowA1] = rb1.z; Bs[buf][kc1 + 3][rowA1] = rb1.w;
    };

    float4 pa0, pa1, pb0, pb1;
    loadTile(0, pa0, pa1, pb0, pb1);
    storeTile(0, pa0, pa1, pb0, pb1);
    __syncthreads();

    for (int kt = 0; kt < numTiles; kt++) {
        int cur = kt & 1;
        bool more = (kt + 1) < numTiles;
        if (more) loadTile(kt + 1, pa0, pa1, pb0, pb1);
#pragma unroll
        for (int k = 0; k < 16; k++) {
            float4 a0 = *(const float4*)&As[cur][k][ty << 3];
            float4 a1 = *(const float4*)&As[cur][k][(ty << 3) + 4];
            float4 b0 = *(const float4*)&Bs[cur][k][tx << 3];
            float4 b1 = *(const float4*)&Bs[cur][k][(tx << 3) + 4];
            float av[8] = {a0.x, a0.y, a0.z, a0.w, a1.x, a1.y, a1.z, a1.w};
            float bv[8] = {b0.x, b0.y, b0.z, b0.w, b1.x, b1.y, b1.z, b1.w};
#pragma unroll
            for (int i = 0; i < 8; i++)
#pragma unroll
                for (int j = 0; j < 8; j++) acc[i][j] += av[i] * bv[j];
        }
        __syncthreads();
        if (more) {
            storeTile(1 - cur, pa0, pa1, pb0, pb1);
            __syncthreads();
        }
    }

    // epilogue
#pragma unroll
    for (int i = 0; i < 8; i++) {
        int m = m0 + (ty << 3) + i;
        if (m >= M) continue;
        int n = n0 + (tx << 3);
        float4 o0, o1;
        o0.x = acc[i][0]; o0.y = acc[i][1]; o0.z = acc[i][2]; o0.w = acc[i][3];
        o1.x = acc[i][4]; o1.y = acc[i][5]; o1.z = acc[i][6]; o1.w = acc[i][7];
        if (bias) {
            const float4 bb0 = *(const float4*)(bias + n);
            const float4 bb1 = *(const float4*)(bias + n + 4);
            o0.x += bb0.x; o0.y += bb0.y; o0.z += bb0.z; o0.w += bb0.w;
            o1.x += bb1.x; o1.y += bb1.y; o1.z += bb1.z; o1.w += bb1.w;
        }
        if (relu) {
            o0.x = fmaxf(o0.x, 0.f); o0.y = fmaxf(o0.y, 0.f); o0.z = fmaxf(o0.z, 0.f); o0.w = fmaxf(o0.w, 0.f);
            o1.x = fmaxf(o1.x, 0.f); o1.y = fmaxf(o1.y, 0.f); o1.z = fmaxf(o1.z, 0.f); o1.w = fmaxf(o1.w, 0.f);
        }
        *(float4*)(C + (size_t)m * N + n) = o0;
        *(float4*)(C + (size_t)m * N + n + 4) = o1;
    }
}

// ---------------- bias combine ----------------
__global__ __launch_bounds__(256) void bias2_kernel(const float* a, const float* b, float* o, int n) {
    int i = blockIdx.x * blockDim.x + threadIdx.x;
    if (i < n) o[i] = a[i] + b[i];
}

// ---------------- LSTM recurrence (2 batch elems per CTA, 512 threads) ----------------
__global__ __launch_bounds__(512) void lstm_rec_kernel(
                                const float* __restrict__ gx,   // B*T*512, x@Wih^T + bih + bhh
                                const float* __restrict__ Whh,  // 512 x 128
                                float* __restrict__ hout) {     // B*T*128
    const int BPC = 2;
    int b0 = blockIdx.x * BPC;
    int j = threadIdx.x;  // 0..511 (gate row)
    __shared__ float sh_h[BPC][HH];
    __shared__ float sh_c[BPC][HH];
    __shared__ float sh_g[BPC][4 * HH];
    if (j < HH) {
        sh_h[0][j] = 0.f; sh_c[0][j] = 0.f;
        sh_h[1][j] = 0.f; sh_c[1][j] = 0.f;
    }
    __syncthreads();
    const float4* W4 = (const float4*)(Whh + (size_t)j * HH);
    for (int t = 0; t < TT; t++) {
        float acc0 = gx[((size_t)(b0 + 0) * TT + t) * 512 + j];
        float acc1 = gx[((size_t)(b0 + 1) * TT + t) * 512 + j];
#pragma unroll 8
        for (int k = 0; k < 32; k++) {
            float4 w  = W4[k];
            float4 h0 = ((const float4*)sh_h[0])[k];
            float4 h1 = ((const float4*)sh_h[1])[k];
            acc0 += w.x * h0.x + w.y * h0.y + w.z * h0.z + w.w * h0.w;
            acc1 += w.x * h1.x + w.y * h1.y + w.z * h1.z + w.w * h1.w;
        }
        sh_g[0][j] = acc0;
        sh_g[1][j] = acc1;
        __syncthreads();
        if (j < 2 * HH) {
            int bb = j >> 7, jj = j & 127;
            float gi = sh_g[bb][jj];
            float gf = sh_g[bb][HH + jj];
            float gg = sh_g[bb][2 * HH + jj];
            float go = sh_g[bb][3 * HH + jj];
            float c = sigf(gf) * sh_c[bb][jj] + sigf(gi) * tanhf(gg);
            sh_c[bb][jj] = c;
            float h = sigf(go) * tanhf(c);
            sh_h[bb][jj] = h;
            hout[((size_t)(b0 + bb) * TT + t) * HH + jj] = h;
        }
        __syncthreads();
    }
}

// ---------------- attention: only last query row needed ----------------
__global__ __launch_bounds__(256) void attn_last_kernel(const float* __restrict__ qkv, float* __restrict__ olast) {
    int gidx = blockIdx.x * blockDim.x + threadIdx.x;
    int w = gidx >> 5;                // 0..127 : (b, head)
    if (w >= BB * 2) return;
    int lane = threadIdx.x & 31;
    int wl = threadIdx.x >> 5;
    int b = w >> 1, h = w & 1;
    const float* base = qkv + (size_t)b * TT * 384;
    const float* q = base + 49 * 384 + h * 64;
    float q0 = q[lane], q1 = q[lane + 32];
    __shared__ float sc[8][TT];
    for (int j = 0; j < TT; j++) {
        const float* kp = base + j * 384 + 128 + h * 64;
        float p = q0 * kp[lane] + q1 * kp[lane + 32];
#pragma unroll
        for (int o = 16; o; o >>= 1) p += __shfl_down_sync(0xffffffffu, p, o);
        if (lane == 0) sc[wl][j] = p * 0.125f;   // /sqrt(64)
    }
    __syncwarp();
    float v0 = (lane < TT) ? sc[wl][lane] : -1e30f;
    float v1 = (lane + 32 < TT) ? sc[wl][lane + 32] : -1e30f;
    float mx = fmaxf(v0, v1);
#pragma unroll
    for (int o = 16; o; o >>= 1) mx = fmaxf(mx, __shfl_xor_sync(0xffffffffu, mx, o));
    float e0 = (lane < TT) ? expf(v0 - mx) : 0.f;
    float e1 = (lane + 32 < TT) ? expf(v1 - mx) : 0.f;
    float s = e0 + e1;
#pragma unroll
    for (int o = 16; o; o >>= 1) s += __shfl_xor_sync(0xffffffffu, s, o);
    float inv = 1.0f / s;
    if (lane < TT) sc[wl][lane] = e0 * inv;
    if (lane + 32 < TT) sc[wl][lane + 32] = e1 * inv;
    __syncwarp();
    float a0 = 0.f, a1 = 0.f;
    for (int j = 0; j < TT; j++) {
        float wj = sc[wl][j];
        const float* vp = base + j * 384 + 256 + h * 64;
        a0 += wj * vp[lane];
        a1 += wj * vp[lane + 32];
    }
    olast[b * HH + h * 64 + lane] = a0;
    olast[b * HH + h * 64 + lane + 32] = a1;
}

// ---------------- final: out-proj (last row) + MLP head ----------------
__global__ __launch_bounds__(128) void head_kernel(const float* __restrict__ olast,
                            const float* __restrict__ Wout, const float* __restrict__ bout,
                            const float* __restrict__ W1, const float* __restrict__ b1,
                            const float* __restrict__ W2, const float* __restrict__ b2,
                            float* __restrict__ pred) {
    int b = blockIdx.x;
    int j = threadIdx.x;  // 128
    __shared__ float o[HH], a[HH], hid[64];
    o[j] = olast[b * HH + j];
    __syncthreads();
    {
        float acc = bout[j];
        const float* w = Wout + (size_t)j * HH;
#pragma unroll 4
        for (int k = 0; k < HH; k++) acc += o[k] * w[k];
        a[j] = acc;
    }
    __syncthreads();
    if (j < 64) {
        float acc = b1[j];
        const float* w = W1 + (size_t)j * HH;
#pragma unroll 4
        for (int k = 0; k < HH; k++) acc += a[k] * w[k];
        hid[j] = fmaxf(acc, 0.0f);
    }
    __syncthreads();
    if (j == 0) {
        float p = b2[0];
#pragma unroll
        for (int k = 0; k < 64; k++) p += hid[k] * W2[k];
        pred[b] = p;
    }
}

// ---------------- host launch ----------------
extern "C" void kernel_launch(void* const* d_in, const int* in_sizes, int n_in,
                              void* d_out, int out_size) {
    (void)in_sizes; (void)n_in; (void)out_size;
    const float* x     = (const float*)d_in[0];
    const int*   eidx  = (const int*)d_in[1];
    const float* tseq  = (const float*)d_in[2];
    const float* W_red = (const float*)d_in[3];
    const float* b_red = (const float*)d_in[4];
    const float* s1Wl  = (const float*)d_in[5];
    const float* s1bl  = (const float*)d_in[6];
    const float* s1Wr  = (const float*)d_in[7];
    const float* s2Wl  = (const float*)d_in[8];
    const float* s2bl  = (const float*)d_in[9];
    const float* s2Wr  = (const float*)d_in[10];
    const float* Wih0  = (const float*)d_in[11];
    const float* Whh0  = (const float*)d_in[12];
    const float* bih0  = (const float*)d_in[13];
    const float* bhh0  = (const float*)d_in[14];
    const float* Wih1  = (const float*)d_in[15];
    const float* Whh1  = (const float*)d_in[16];
    const float* bih1  = (const float*)d_in[17];
    const float* bhh1  = (const float*)d_in[18];
    const float* Win   = (const float*)d_in[19];
    const float* binp  = (const float*)d_in[20];
    const float* Wout  = (const float*)d_in[21];
    const float* bout  = (const float*)d_in[22];
    const float* hW1   = (const float*)d_in[23];
    const float* hb1   = (const float*)d_in[24];
    const float* hW2   = (const float*)d_in[25];
    const float* hb2   = (const float*)d_in[26];

    float* out     = (float*)d_out;
    float* pred    = out;        // (64,1)
    float* spatial = out + BB;   // (50000,128)

    const int* src = eidx;
    const int* dst = eidx + EE;

    void* p;
    cudaGetSymbolAddress(&p, g_reduced); float* reduced = (float*)p;
    cudaGetSymbolAddress(&p, g_agg);     float* agg     = (float*)p;
    cudaGetSymbolAddress(&p, g_s);       float* sbuf    = (float*)p;
    cudaGetSymbolAddress(&p, g_invdeg);  float* invdeg  = (float*)p;
    cudaGetSymbolAddress(&p, g_deg);     int*   deg     = (int*)p;
    cudaGetSymbolAddress(&p, g_ts);      float* ts      = (float*)p;
    cudaGetSymbolAddress(&p, g_gates);   float* gates   = (float*)p;
    cudaGetSymbolAddress(&p, g_h1);      float* h1      = (float*)p;
    cudaGetSymbolAddress(&p, g_h2);      float* h2      = (float*)p;
    cudaGetSymbolAddress(&p, g_qkv);     float* qkv     = (float*)p;
    cudaGetSymbolAddress(&p, g_olast);   float* olast   = (float*)p;
    cudaGetSymbolAddress(&p, g_bias0);   float* bias0   = (float*)p;
    cudaGetSymbolAddress(&p, g_bias1);   float* bias1   = (float*)p;

    // ---- graph branch ----
    cudaMemsetAsync(agg, 0, sizeof(float) * (size_t)NND * HH);
    cudaMemsetAsync(deg, 0, sizeof(int) * NND);
    deg_kernel<<<(EE + 255) / 256, 256>>>(dst, deg, EE);
    invdeg_kernel<<<(NND + 255) / 256, 256>>>(deg, invdeg, NND);

    // reduced = x @ W_red^T + b_red
    gemm_nt_kernel<<<dim3((NND + 127) / 128, HH / 128), 256>>>(
        x, W_red, x, W_red, nullptr, b_red, reduced, NND, HH, FF, FF, 0);

    // agg += reduced[src] scattered to dst
    {
        long long tot = (long long)EE * 32;
        scatter_add_kernel<<<(unsigned)((tot + 255) / 256), 256>>>(reduced, src, dst, agg, EE);
    }
    // s = relu((agg*invdeg) @ Wl1^T + bl1 + reduced @ Wr1^T)
    gemm_nt_kernel<<<dim3((NND + 127) / 128, HH / 128), 256>>>(
        agg, s1Wl, reduced, s1Wr, invdeg, s1bl, sbuf, NND, HH, 2 * HH, HH, 1);

    cudaMemsetAsync(agg, 0, sizeof(float) * (size_t)NND * HH);
    {
        long long tot = (long long)EE * 32;
        scatter_add_kernel<<<(unsigned)((tot + 255) / 256), 256>>>(sbuf, src, dst, agg, EE);
    }
    // spatial = relu((agg*invdeg) @ Wl2^T + bl2 + s @ Wr2^T)
    gemm_nt_kernel<<<dim3((NND + 127) / 128, HH / 128), 256>>>(
        agg, s2Wl, sbuf, s2Wr, invdeg, s2bl, spatial, NND, HH, 2 * HH, HH, 1);

    // ---- temporal branch ----
    // ts = time_sequence @ W_red^T + b_red   (3200 x 128)
    gemm_nt_kernel<<<dim3((BB * TT + 127) / 128, HH / 128), 256>>>(
        tseq, W_red, tseq, W_red, nullptr, b_red, ts, BB * TT, HH, FF, FF, 0);

    bias2_kernel<<<2, 256>>>(bih0, bhh0, bias0, 4 * HH);
    bias2_kernel<<<2, 256>>>(bih1, bhh1, bias1, 4 * HH);

    // gates0 = ts @ Wih0^T + (bih0+bhh0)
    gemm_nt_kernel<<<dim3((BB * TT + 127) / 128, (4 * HH) / 128), 256>>>(
        ts, Wih0, ts, Wih0, nullptr, bias0, gates, BB * TT, 4 * HH, HH, HH, 0);
    lstm_rec_kernel<<<BB / 2, 512>>>(gates, Whh0, h1);

    // gates1 = h1 @ Wih1^T + (bih1+bhh1)
    gemm_nt_kernel<<<dim3((BB * TT + 127) / 128, (4 * HH) / 128), 256>>>(
        h1, Wih1, h1, Wih1, nullptr, bias1, gates, BB * TT, 4 * HH, HH, HH, 0);
    lstm_rec_kernel<<<BB / 2, 512>>>(gates, Whh1, h2);

    // qkv = h2 @ Win^T + bin   (3200 x 384)
    gemm_nt_kernel<<<dim3((BB * TT + 127) / 128, (3 * HH) / 128), 256>>>(
        h2, Win, h2, Win, nullptr, binp, qkv, BB * TT, 3 * HH, HH, HH, 0);

    attn_last_kernel<<<16, 256>>>(qkv, olast);
    head_kernel<<<BB, HH>>>(olast, Wout, bout, hW1, hb1, hW2, hb2, pred);
}

// round 5
// speedup vs baseline: 1.1307x; 1.1307x over previous
#include <cuda_runtime.h>
#include <cuda_bf16.h>
#include <math.h>
#include <stdint.h>

// Problem constants
#define NND 50000
#define FF  256
#define HH  128
#define EE  800000
#define BB  64
#define TT  50

// ---------------- device scratch ----------------
__device__ float g_reduced[NND * HH];
__device__ float g_agg[NND * HH];
__device__ float g_s[NND * HH];
__device__ float g_invdeg[NND];
__device__ int   g_deg[NND];
__device__ float g_ts[BB * TT * HH];
__device__ float g_gates[BB * TT * 4 * HH];
__device__ float g_h1[BB * TT * HH];
__device__ float g_h2[BB * TT * HH];
__device__ float g_qkv[BB * TT * 3 * HH];
__device__ float g_olast[BB * HH];
__device__ float g_bias0[4 * HH];
__device__ float g_bias1[4 * HH];

__device__ __forceinline__ float sigf(float x) { return 1.0f / (1.0f + __expf(-x)); }

__device__ __forceinline__ uint32_t f2tf32(float f) {
    uint32_t u;
    asm("cvt.rna.tf32.f32 %0, %1;" : "=r"(u) : "f"(f));
    return u;
}

__device__ __forceinline__ void mma_tf32(float* d, const uint32_t* a, const uint32_t* b) {
    asm volatile("mma.sync.aligned.m16n8k8.row.col.f32.tf32.tf32.f32 "
                 "{%0,%1,%2,%3}, {%4,%5,%6,%7}, {%8,%9}, {%0,%1,%2,%3};"
                 : "+f"(d[0]), "+f"(d[1]), "+f"(d[2]), "+f"(d[3])
                 : "r"(a[0]), "r"(a[1]), "r"(a[2]), "r"(a[3]), "r"(b[0]), "r"(b[1]));
}

// ---------------- degree kernels ----------------
__global__ __launch_bounds__(256) void deg_kernel(const int* __restrict__ dst, int* __restrict__ deg, int E) {
    int i = blockIdx.x * blockDim.x + threadIdx.x;
    if (i < E) atomicAdd(&deg[dst[i]], 1);
}

__global__ __launch_bounds__(256) void invdeg_kernel(const int* __restrict__ deg, float* __restrict__ inv, int n) {
    int i = blockIdx.x * blockDim.x + threadIdx.x;
    if (i < n) inv[i] = 1.0f / (float)max(deg[i], 1);
}

// ---------------- scatter-add (one warp per edge, v4 reductions) ----------------
__global__ __launch_bounds__(256) void scatter_add_kernel(const float* __restrict__ feat,
                                   const int* __restrict__ src,
                                   const int* __restrict__ dst,
                                   float* __restrict__ agg, int E) {
    int idx = blockIdx.x * blockDim.x + threadIdx.x;
    int e = idx >> 5;
    if (e >= E) return;
    int lane = idx & 31;
    int s = __ldg(src + e);
    int d = __ldg(dst + e);
    float4 v = *(const float4*)(feat + (size_t)s * HH + lane * 4);
    float* p = agg + (size_t)d * HH + lane * 4;
    asm volatile("red.global.add.v4.f32 [%0], {%1,%2,%3,%4};"
                 :: "l"(p), "f"(v.x), "f"(v.y), "f"(v.z), "f"(v.w) : "memory");
}

// ---------------- tf32 tensor-core NT GEMM ----------------
// C(MxN) = A1(MxKsplit)@B1(NxKsplit)^T + A2(Mx(Ktot-Ksplit))@B2(Nx..)^T + bias, opt relu.
// Rows of A1 optionally scaled by rowscale[m]. Requirements:
//   N multiple of 128, Ktot & Ksplit multiples of 16.
#define KT 16
__global__ __launch_bounds__(256) void gemm_tf32_kernel(
        const float* __restrict__ A1, const float* __restrict__ B1,
        const float* __restrict__ A2, const float* __restrict__ B2,
        const float* __restrict__ rowscale,
        const float* __restrict__ bias,
        float* __restrict__ C,
        int M, int N, int Ktot, int Ksplit, int relu) {
    __shared__ uint32_t As[2][KT][136];
    __shared__ uint32_t Bs[2][KT][136];
    const int tid  = threadIdx.x;
    const int m0   = blockIdx.x * 128;
    const int n0   = blockIdx.y * 128;
    const int warp = tid >> 5, lane = tid & 31;
    const int wm   = (warp >> 1) * 32;   // 4 warps in m
    const int wn   = (warp & 1) * 64;    // 2 warps in n
    const int g    = lane >> 2, c = lane & 3;
    const bool haveScale = (rowscale != nullptr);

    float acc[2][8][4];
#pragma unroll
    for (int mt = 0; mt < 2; mt++)
#pragma unroll
        for (int nt = 0; nt < 8; nt++)
#pragma unroll
            for (int r = 0; r < 4; r++) acc[mt][nt][r] = 0.0f;

    const int numSlabs = Ktot / KT;

    // each thread handles 2 tasks per array: task = (row 0..127, kchunk 0..3)
    const int row0 = tid & 127,        kc0 = tid >> 7;          // kc0 in {0,1}
    const int row1 = tid & 127,        kc1 = (tid >> 7) + 2;    // {2,3}

    float4 pa[2], pb[2];

    auto loadSlab = [&](int s) {
        int kbase = s * KT;
        const float* A; const float* Bm; int lda, koff; bool sc;
        if (kbase < Ksplit) { A = A1; Bm = B1; lda = Ksplit;        koff = kbase;          sc = haveScale; }
        else                { A = A2; Bm = B2; lda = Ktot - Ksplit; koff = kbase - Ksplit; sc = false; }
        {
            int m = m0 + row0;
            pa[0] = make_float4(0.f, 0.f, 0.f, 0.f);
            if (m < M) {
                pa[0] = *(const float4*)(A + (size_t)m * lda + koff + kc0 * 4);
                if (sc) { float sv = rowscale[m]; pa[0].x *= sv; pa[0].y *= sv; pa[0].z *= sv; pa[0].w *= sv; }
            }
            pb[0] = *(const float4*)(Bm + (size_t)(n0 + row0) * lda + koff + kc0 * 4);
        }
        {
            int m = m0 + row1;
            pa[1] = make_float4(0.f, 0.f, 0.f, 0.f);
            if (m < M) {
                pa[1] = *(const float4*)(A + (size_t)m * lda + koff + kc1 * 4);
                if (sc) { float sv = rowscale[m]; pa[1].x *= sv; pa[1].y *= sv; pa[1].z *= sv; pa[1].w *= sv; }
            }
            pb[1] = *(const float4*)(Bm + (size_t)(n0 + row1) * lda + koff + kc1 * 4);
        }
    };

    auto storeSlab = [&](int buf) {
        int k0 = kc0 * 4;
        As[buf][k0 + 0][row0] = f2tf32(pa[0].x); As[buf][k0 + 1][row0] = f2tf32(pa[0].y);
        As[buf][k0 + 2][row0] = f2tf32(pa[0].z); As[buf][k0 + 3][row0] = f2tf32(pa[0].w);
        Bs[buf][k0 + 0][row0] = f2tf32(pb[0].x); Bs[buf][k0 + 1][row0] = f2tf32(pb[0].y);
        Bs[buf][k0 + 2][row0] = f2tf32(pb[0].z); Bs[buf][k0 + 3][row0] = f2tf32(pb[0].w);
        int k1 = kc1 * 4;
        As[buf][k1 + 0][row1] = f2tf32(pa[1].x); As[buf][k1 + 1][row1] = f2tf32(pa[1].y);
        As[buf][k1 + 2][row1] = f2tf32(pa[1].z); As[buf][k1 + 3][row1] = f2tf32(pa[1].w);
        Bs[buf][k1 + 0][row1] = f2tf32(pb[1].x); Bs[buf][k1 + 1][row1] = f2tf32(pb[1].y);
        Bs[buf][k1 + 2][row1] = f2tf32(pb[1].z); Bs[buf][k1 + 3][row1] = f2tf32(pb[1].w);
    };

    loadSlab(0);
    storeSlab(0);
    __syncthreads();

    for (int s = 0; s < numSlabs; s++) {
        int buf = s & 1;
        bool more = (s + 1) < numSlabs;
        if (more) loadSlab(s + 1);
#pragma unroll
        for (int k8 = 0; k8 < 2; k8++) {
            int kb = k8 * 8;
            uint32_t afr[2][4], bfr[8][2];
#pragma unroll
            for (int mt = 0; mt < 2; mt++) {
                int mb = wm + mt * 16 + g;
                afr[mt][0] = As[buf][kb + c][mb];
                afr[mt][1] = As[buf][kb + c][mb + 8];
                afr[mt][2] = As[buf][kb + c + 4][mb];
                afr[mt][3] = As[buf][kb + c + 4][mb + 8];
            }
#pragma unroll
            for (int nt = 0; nt < 8; nt++) {
                int nb = wn + nt * 8 + g;
                bfr[nt][0] = Bs[buf][kb + c][nb];
                bfr[nt][1] = Bs[buf][kb + c + 4][nb];
            }
#pragma unroll
            for (int mt = 0; mt < 2; mt++)
#pragma unroll
                for (int nt = 0; nt < 8; nt++)
                    mma_tf32(acc[mt][nt], afr[mt], bfr[nt]);
        }
        __syncthreads();
        if (more) {
            storeSlab(1 - buf);
            __syncthreads();
        }
    }

    // epilogue
#pragma unroll
    for (int mt = 0; mt < 2; mt++) {
#pragma unroll
        for (int nt = 0; nt < 8; nt++) {
            const float* d = acc[mt][nt];
            int mrow = m0 + wm + mt * 16 + g;
            int ncol = n0 + wn + nt * 8 + 2 * c;
            float b0v = 0.f, b1v = 0.f;
            if (bias) { b0v = bias[ncol]; b1v = bias[ncol + 1]; }
            float v0 = d[0] + b0v, v1 = d[1] + b1v;
            float v2 = d[2] + b0v, v3 = d[3] + b1v;
            if (relu) {
                v0 = fmaxf(v0, 0.f); v1 = fmaxf(v1, 0.f);
                v2 = fmaxf(v2, 0.f); v3 = fmaxf(v3, 0.f);
            }
            if (mrow < M)     *(float2*)(C + (size_t)mrow * N + ncol)       = make_float2(v0, v1);
            if (mrow + 8 < M) *(float2*)(C + (size_t)(mrow + 8) * N + ncol) = make_float2(v2, v3);
        }
    }
}

// ---------------- bias combine ----------------
__global__ __launch_bounds__(256) void bias2_kernel(const float* a, const float* b, float* o, int n) {
    int i = blockIdx.x * blockDim.x + threadIdx.x;
    if (i < n) o[i] = a[i] + b[i];
}

// ---------------- LSTM recurrence (2 batch elems per CTA, 512 threads) ----------------
__global__ __launch_bounds__(512) void lstm_rec_kernel(
                                const float* __restrict__ gx,   // B*T*512, x@Wih^T + bih + bhh
                                const float* __restrict__ Whh,  // 512 x 128
                                float* __restrict__ hout) {     // B*T*128
    const int BPC = 2;
    int b0 = blockIdx.x * BPC;
    int j = threadIdx.x;  // 0..511 (gate row)
    __shared__ float sh_h[BPC][HH];
    __shared__ float sh_c[BPC][HH];
    __shared__ float sh_g[BPC][4 * HH];
    if (j < HH) {
        sh_h[0][j] = 0.f; sh_c[0][j] = 0.f;
        sh_h[1][j] = 0.f; sh_c[1][j] = 0.f;
    }
    __syncthreads();
    const float4* W4 = (const float4*)(Whh + (size_t)j * HH);
    for (int t = 0; t < TT; t++) {
        float acc0 = gx[((size_t)(b0 + 0) * TT + t) * 512 + j];
        float acc1 = gx[((size_t)(b0 + 1) * TT + t) * 512 + j];
#pragma unroll 8
        for (int k = 0; k < 32; k++) {
            float4 w  = W4[k];
            float4 h0 = ((const float4*)sh_h[0])[k];
            float4 h1 = ((const float4*)sh_h[1])[k];
            acc0 += w.x * h0.x + w.y * h0.y + w.z * h0.z + w.w * h0.w;
            acc1 += w.x * h1.x + w.y * h1.y + w.z * h1.z + w.w * h1.w;
        }
        sh_g[0][j] = acc0;
        sh_g[1][j] = acc1;
        __syncthreads();
        if (j < 2 * HH) {
            int bb = j >> 7, jj = j & 127;
            float gi = sh_g[bb][jj];
            float gf = sh_g[bb][HH + jj];
            float gg = sh_g[bb][2 * HH + jj];
            float go = sh_g[bb][3 * HH + jj];
            float cc = sigf(gf) * sh_c[bb][jj] + sigf(gi) * tanhf(gg);
            sh_c[bb][jj] = cc;
            float h = sigf(go) * tanhf(cc);
            sh_h[bb][jj] = h;
            hout[((size_t)(b0 + bb) * TT + t) * HH + jj] = h;
        }
        __syncthreads();
    }
}

// ---------------- attention: only last query row needed ----------------
__global__ __launch_bounds__(256) void attn_last_kernel(const float* __restrict__ qkv, float* __restrict__ olast) {
    int gidx = blockIdx.x * blockDim.x + threadIdx.x;
    int w = gidx >> 5;                // 0..127 : (b, head)
    if (w >= BB * 2) return;
    int lane = threadIdx.x & 31;
    int wl = threadIdx.x >> 5;
    int b = w >> 1, h = w & 1;
    const float* base = qkv + (size_t)b * TT * 384;
    const float* q = base + 49 * 384 + h * 64;
    float q0 = q[lane], q1 = q[lane + 32];
    __shared__ float sc[8][TT];
    for (int j = 0; j < TT; j++) {
        const float* kp = base + j * 384 + 128 + h * 64;
        float p = q0 * kp[lane] + q1 * kp[lane + 32];
#pragma unroll
        for (int o = 16; o; o >>= 1) p += __shfl_down_sync(0xffffffffu, p, o);
        if (lane == 0) sc[wl][j] = p * 0.125f;   // /sqrt(64)
    }
    __syncwarp();
    float v0 = (lane < TT) ? sc[wl][lane] : -1e30f;
    float v1 = (lane + 32 < TT) ? sc[wl][lane + 32] : -1e30f;
    float mx = fmaxf(v0, v1);
#pragma unroll
    for (int o = 16; o; o >>= 1) mx = fmaxf(mx, __shfl_xor_sync(0xffffffffu, mx, o));
    float e0 = (lane < TT) ? expf(v0 - mx) : 0.f;
    float e1 = (lane + 32 < TT) ? expf(v1 - mx) : 0.f;
    float s = e0 + e1;
#pragma unroll
    for (int o = 16; o; o >>= 1) s += __shfl_xor_sync(0xffffffffu, s, o);
    float inv = 1.0f / s;
    if (lane < TT) sc[wl][lane] = e0 * inv;
    if (lane + 32 < TT) sc[wl][lane + 32] = e1 * inv;
    __syncwarp();
    float a0 = 0.f, a1 = 0.f;
    for (int j = 0; j < TT; j++) {
        float wj = sc[wl][j];
        const float* vp = base + j * 384 + 256 + h * 64;
        a0 += wj * vp[lane];
        a1 += wj * vp[lane + 32];
    }
    olast[b * HH + h * 64 + lane] = a0;
    olast[b * HH + h * 64 + lane + 32] = a1;
}

// ---------------- final: out-proj (last row) + MLP head ----------------
__global__ __launch_bounds__(128) void head_kernel(const float* __restrict__ olast,
                            const float* __restrict__ Wout, const float* __restrict__ bout,
                            const float* __restrict__ W1, const float* __restrict__ b1,
                            const float* __restrict__ W2, const float* __restrict__ b2,
                            float* __restrict__ pred) {
    int b = blockIdx.x;
    int j = threadIdx.x;  // 128
    __shared__ float o[HH], a[HH], hid[64];
    o[j] = olast[b * HH + j];
    __syncthreads();
    {
        float acc = bout[j];
        const float* w = Wout + (size_t)j * HH;
#pragma unroll 4
        for (int k = 0; k < HH; k++) acc += o[k] * w[k];
        a[j] = acc;
    }
    __syncthreads();
    if (j < 64) {
        float acc = b1[j];
        const float* w = W1 + (size_t)j * HH;
#pragma unroll 4
        for (int k = 0; k < HH; k++) acc += a[k] * w[k];
        hid[j] = fmaxf(acc, 0.0f);
    }
    __syncthreads();
    if (j == 0) {
        float p = b2[0];
#pragma unroll
        for (int k = 0; k < 64; k++) p += hid[k] * W2[k];
        pred[b] = p;
    }
}

// ---------------- host launch ----------------
extern "C" void kernel_launch(void* const* d_in, const int* in_sizes, int n_in,
                              void* d_out, int out_size) {
    (void)in_sizes; (void)n_in; (void)out_size;
    const float* x     = (const float*)d_in[0];
    const int*   eidx  = (const int*)d_in[1];
    const float* tseq  = (const float*)d_in[2];
    const float* W_red = (const float*)d_in[3];
    const float* b_red = (const float*)d_in[4];
    const float* s1Wl  = (const float*)d_in[5];
    const float* s1bl  = (const float*)d_in[6];
    const float* s1Wr  = (const float*)d_in[7];
    const float* s2Wl  = (const float*)d_in[8];
    const float* s2bl  = (const float*)d_in[9];
    const float* s2Wr  = (const float*)d_in[10];
    const float* Wih0  = (const float*)d_in[11];
    const float* Whh0  = (const float*)d_in[12];
    const float* bih0  = (const float*)d_in[13];
    const float* bhh0  = (const float*)d_in[14];
    const float* Wih1  = (const float*)d_in[15];
    const float* Whh1  = (const float*)d_in[16];
    const float* bih1  = (const float*)d_in[17];
    const float* bhh1  = (const float*)d_in[18];
    const float* Win   = (const float*)d_in[19];
    const float* binp  = (const float*)d_in[20];
    const float* Wout  = (const float*)d_in[21];
    const float* bout  = (const float*)d_in[22];
    const float* hW1   = (const float*)d_in[23];
    const float* hb1   = (const float*)d_in[24];
    const float* hW2   = (const float*)d_in[25];
    const float* hb2   = (const float*)d_in[26];

    float* out     = (float*)d_out;
    float* pred    = out;        // (64,1)
    float* spatial = out + BB;   // (50000,128)

    const int* src = eidx;
    const int* dst = eidx + EE;

    void* p;
    cudaGetSymbolAddress(&p, g_reduced); float* reduced = (float*)p;
    cudaGetSymbolAddress(&p, g_agg);     float* agg     = (float*)p;
    cudaGetSymbolAddress(&p, g_s);       float* sbuf    = (float*)p;
    cudaGetSymbolAddress(&p, g_invdeg);  float* invdeg  = (float*)p;
    cudaGetSymbolAddress(&p, g_deg);     int*   deg     = (int*)p;
    cudaGetSymbolAddress(&p, g_ts);      float* ts      = (float*)p;
    cudaGetSymbolAddress(&p, g_gates);   float* gates   = (float*)p;
    cudaGetSymbolAddress(&p, g_h1);      float* h1      = (float*)p;
    cudaGetSymbolAddress(&p, g_h2);      float* h2      = (float*)p;
    cudaGetSymbolAddress(&p, g_qkv);     float* qkv     = (float*)p;
    cudaGetSymbolAddress(&p, g_olast);   float* olast   = (float*)p;
    cudaGetSymbolAddress(&p, g_bias0);   float* bias0   = (float*)p;
    cudaGetSymbolAddress(&p, g_bias1);   float* bias1   = (float*)p;

    // ---- graph branch ----
    cudaMemsetAsync(agg, 0, sizeof(float) * (size_t)NND * HH);
    cudaMemsetAsync(deg, 0, sizeof(int) * NND);
    deg_kernel<<<(EE + 255) / 256, 256>>>(dst, deg, EE);
    invdeg_kernel<<<(NND + 255) / 256, 256>>>(deg, invdeg, NND);

    // reduced = x @ W_red^T + b_red
    gemm_tf32_kernel<<<dim3((NND + 127) / 128, HH / 128), 256>>>(
        x, W_red, x, W_red, nullptr, b_red, reduced, NND, HH, FF, FF, 0);

    // agg += reduced[src] scattered to dst
    {
        long long tot = (long long)EE * 32;
        scatter_add_kernel<<<(unsigned)((tot + 255) / 256), 256>>>(reduced, src, dst, agg, EE);
    }

    // ts = time_sequence @ W_red^T + b_red   (3200 x 128)  — independent, placed here
    // so the ncu-captured launch (#6) is the sage1 mma GEMM below.
    gemm_tf32_kernel<<<dim3((BB * TT + 127) / 128, HH / 128), 256>>>(
        tseq, W_red, tseq, W_red, nullptr, b_red, ts, BB * TT, HH, FF, FF, 0);

    // s = relu((agg*invdeg) @ Wl1^T + bl1 + reduced @ Wr1^T)
    gemm_tf32_kernel<<<dim3((NND + 127) / 128, HH / 128), 256>>>(
        agg, s1Wl, reduced, s1Wr, invdeg, s1bl, sbuf, NND, HH, 2 * HH, HH, 1);

    cudaMemsetAsync(agg, 0, sizeof(float) * (size_t)NND * HH);
    {
        long long tot = (long long)EE * 32;
        scatter_add_kernel<<<(unsigned)((tot + 255) / 256), 256>>>(sbuf, src, dst, agg, EE);
    }
    // spatial = relu((agg*invdeg) @ Wl2^T + bl2 + s @ Wr2^T)
    gemm_tf32_kernel<<<dim3((NND + 127) / 128, HH / 128), 256>>>(
        agg, s2Wl, sbuf, s2Wr, invdeg, s2bl, spatial, NND, HH, 2 * HH, HH, 1);

    // ---- temporal branch ----
    bias2_kernel<<<2, 256>>>(bih0, bhh0, bias0, 4 * HH);
    bias2_kernel<<<2, 256>>>(bih1, bhh1, bias1, 4 * HH);

    // gates0 = ts @ Wih0^T + (bih0+bhh0)
    gemm_tf32_kernel<<<dim3((BB * TT + 127) / 128, (4 * HH) / 128), 256>>>(
        ts, Wih0, ts, Wih0, nullptr, bias0, gates, BB * TT, 4 * HH, HH, HH, 0);
    lstm_rec_kernel<<<BB / 2, 512>>>(gates, Whh0, h1);

    // gates1 = h1 @ Wih1^T + (bih1+bhh1)
    gemm_tf32_kernel<<<dim3((BB * TT + 127) / 128, (4 * HH) / 128), 256>>>(
        h1, Wih1, h1, Wih1, nullptr, bias1, gates, BB * TT, 4 * HH, HH, HH, 0);
    lstm_rec_kernel<<<BB / 2, 512>>>(gates, Whh1, h2);

    // qkv = h2 @ Win^T + bin   (3200 x 384)
    gemm_tf32_kernel<<<dim3((BB * TT + 127) / 128, (3 * HH) / 128), 256>>>(
        h2, Win, h2, Win, nullptr, binp, qkv, BB * TT, 3 * HH, HH, HH, 0);

    attn_last_kernel<<<16, 256>>>(qkv, olast);
    head_kernel<<<BB, HH>>>(olast, Wout, bout, hW1, hb1, hW2, hb2, pred);
}

// round 6
// speedup vs baseline: 1.1310x; 1.0003x over previous
#include <cuda_runtime.h>
#include <cuda_bf16.h>
#include <math.h>
#include <stdint.h>

// Problem constants
#define NND 50000
#define FF  256
#define HH  128
#define EE  800000
#define BB  64
#define TT  50

// ---------------- device scratch ----------------
__device__ float g_reduced[NND * HH];
__device__ float g_agg[NND * HH];
__device__ float g_s[NND * HH];
__device__ float g_invdeg[NND];
__device__ int   g_deg[NND];
__device__ float g_ts[BB * TT * HH];
__device__ float g_gates[BB * TT * 4 * HH];
__device__ float g_h1[BB * TT * HH];
__device__ float g_h2[BB * TT * HH];
__device__ float g_qkv[BB * TT * 3 * HH];
__device__ float g_olast[BB * HH];
__device__ float g_bias0[4 * HH];
__device__ float g_bias1[4 * HH];
__device__ float g_WhhT0[HH * 4 * HH];   // [128][512] transposed Whh0
__device__ float g_WhhT1[HH * 4 * HH];   // [128][512] transposed Whh1

__device__ __forceinline__ float sigf(float x) { return 1.0f / (1.0f + __expf(-x)); }

__device__ __forceinline__ uint32_t f2tf32(float f) {
    uint32_t u;
    asm("cvt.rna.tf32.f32 %0, %1;" : "=r"(u) : "f"(f));
    return u;
}

__device__ __forceinline__ void mma_tf32(float* d, const uint32_t* a, const uint32_t* b) {
    asm volatile("mma.sync.aligned.m16n8k8.row.col.f32.tf32.tf32.f32 "
                 "{%0,%1,%2,%3}, {%4,%5,%6,%7}, {%8,%9}, {%0,%1,%2,%3};"
                 : "+f"(d[0]), "+f"(d[1]), "+f"(d[2]), "+f"(d[3])
                 : "r"(a[0]), "r"(a[1]), "r"(a[2]), "r"(a[3]), "r"(b[0]), "r"(b[1]));
}

// ---------------- degree kernels ----------------
__global__ __launch_bounds__(256) void deg_kernel(const int* __restrict__ dst, int* __restrict__ deg, int E) {
    int i = blockIdx.x * blockDim.x + threadIdx.x;
    if (i < E) atomicAdd(&deg[dst[i]], 1);
}

__global__ __launch_bounds__(256) void invdeg_kernel(const int* __restrict__ deg, float* __restrict__ inv, int n) {
    int i = blockIdx.x * blockDim.x + threadIdx.x;
    if (i < n) inv[i] = 1.0f / (float)max(deg[i], 1);
}

// ---------------- weight transpose: Whh[512][128] -> WhhT[128][512] ----------------
__global__ __launch_bounds__(256) void transposeW_kernel(const float* __restrict__ W0,
                                                         const float* __restrict__ W1,
                                                         float* __restrict__ T0,
                                                         float* __restrict__ T1) {
    int idx = blockIdx.x * blockDim.x + threadIdx.x;
    if (idx < 512 * 128) {
        int j = idx >> 7;      // gate row 0..511
        int k = idx & 127;     // hidden col 0..127
        T0[k * 512 + j] = W0[idx];
        T1[k * 512 + j] = W1[idx];
    }
}

// ---------------- scatter-add (one warp per edge, v4 reductions) ----------------
__global__ __launch_bounds__(256) void scatter_add_kernel(const float* __restrict__ feat,
                                   const int* __restrict__ src,
                                   const int* __restrict__ dst,
                                   float* __restrict__ agg, int E) {
    int idx = blockIdx.x * blockDim.x + threadIdx.x;
    int e = idx >> 5;
    if (e >= E) return;
    int lane = idx & 31;
    int s = __ldg(src + e);
    int d = __ldg(dst + e);
    float4 v = *(const float4*)(feat + (size_t)s * HH + lane * 4);
    float* p = agg + (size_t)d * HH + lane * 4;
    asm volatile("red.global.add.v4.f32 [%0], {%1,%2,%3,%4};"
                 :: "l"(p), "f"(v.x), "f"(v.y), "f"(v.z), "f"(v.w) : "memory");
}

// ---------------- tf32 tensor-core NT GEMM ----------------
// C(MxN) = A1(MxKsplit)@B1(NxKsplit)^T + A2(Mx(Ktot-Ksplit))@B2(Nx..)^T + bias, opt relu.
// Rows of A1 optionally scaled by rowscale[m]. N multiple of 128, Ktot & Ksplit multiples of 16.
#define KT 16
__global__ __launch_bounds__(256) void gemm_tf32_kernel(
        const float* __restrict__ A1, const float* __restrict__ B1,
        const float* __restrict__ A2, const float* __restrict__ B2,
        const float* __restrict__ rowscale,
        const float* __restrict__ bias,
        float* __restrict__ C,
        int M, int N, int Ktot, int Ksplit, int relu) {
    __shared__ uint32_t As[2][KT][136];
    __shared__ uint32_t Bs[2][KT][136];
    const int tid  = threadIdx.x;
    const int m0   = blockIdx.x * 128;
    const int n0   = blockIdx.y * 128;
    const int warp = tid >> 5, lane = tid & 31;
    const int wm   = (warp >> 1) * 32;   // 4 warps in m
    const int wn   = (warp & 1) * 64;    // 2 warps in n
    const int g    = lane >> 2, c = lane & 3;
    const bool haveScale = (rowscale != nullptr);

    float acc[2][8][4];
#pragma unroll
    for (int mt = 0; mt < 2; mt++)
#pragma unroll
        for (int nt = 0; nt < 8; nt++)
#pragma unroll
            for (int r = 0; r < 4; r++) acc[mt][nt][r] = 0.0f;

    const int numSlabs = Ktot / KT;

    const int row0 = tid & 127, kc0 = tid >> 7;          // kc0 in {0,1}
    const int row1 = tid & 127, kc1 = (tid >> 7) + 2;    // {2,3}

    float4 pa[2], pb[2];

    auto loadSlab = [&](int s) {
        int kbase = s * KT;
        const float* A; const float* Bm; int lda, koff; bool sc;
        if (kbase < Ksplit) { A = A1; Bm = B1; lda = Ksplit;        koff = kbase;          sc = haveScale; }
        else                { A = A2; Bm = B2; lda = Ktot - Ksplit; koff = kbase - Ksplit; sc = false; }
        {
            int m = m0 + row0;
            pa[0] = make_float4(0.f, 0.f, 0.f, 0.f);
            if (m < M) {
                pa[0] = *(const float4*)(A + (size_t)m * lda + koff + kc0 * 4);
                if (sc) { float sv = rowscale[m]; pa[0].x *= sv; pa[0].y *= sv; pa[0].z *= sv; pa[0].w *= sv; }
            }
            pb[0] = *(const float4*)(Bm + (size_t)(n0 + row0) * lda + koff + kc0 * 4);
        }
        {
            int m = m0 + row1;
            pa[1] = make_float4(0.f, 0.f, 0.f, 0.f);
            if (m < M) {
                pa[1] = *(const float4*)(A + (size_t)m * lda + koff + kc1 * 4);
                if (sc) { float sv = rowscale[m]; pa[1].x *= sv; pa[1].y *= sv; pa[1].z *= sv; pa[1].w *= sv; }
            }
            pb[1] = *(const float4*)(Bm + (size_t)(n0 + row1) * lda + koff + kc1 * 4);
        }
    };

    auto storeSlab = [&](int buf) {
        int k0 = kc0 * 4;
        As[buf][k0 + 0][row0] = f2tf32(pa[0].x); As[buf][k0 + 1][row0] = f2tf32(pa[0].y);
        As[buf][k0 + 2][row0] = f2tf32(pa[0].z); As[buf][k0 + 3][row0] = f2tf32(pa[0].w);
        Bs[buf][k0 + 0][row0] = f2tf32(pb[0].x); Bs[buf][k0 + 1][row0] = f2tf32(pb[0].y);
        Bs[buf][k0 + 2][row0] = f2tf32(pb[0].z); Bs[buf][k0 + 3][row0] = f2tf32(pb[0].w);
        int k1 = kc1 * 4;
        As[buf][k1 + 0][row1] = f2tf32(pa[1].x); As[buf][k1 + 1][row1] = f2tf32(pa[1].y);
        As[buf][k1 + 2][row1] = f2tf32(pa[1].z); As[buf][k1 + 3][row1] = f2tf32(pa[1].w);
        Bs[buf][k1 + 0][row1] = f2tf32(pb[1].x); Bs[buf][k1 + 1][row1] = f2tf32(pb[1].y);
        Bs[buf][k1 + 2][row1] = f2tf32(pb[1].z); Bs[buf][k1 + 3][row1] = f2tf32(pb[1].w);
    };

    loadSlab(0);
    storeSlab(0);
    __syncthreads();

    for (int s = 0; s < numSlabs; s++) {
        int buf = s & 1;
        bool more = (s + 1) < numSlabs;
        if (more) loadSlab(s + 1);
#pragma unroll
        for (int k8 = 0; k8 < 2; k8++) {
            int kb = k8 * 8;
            uint32_t afr[2][4], bfr[8][2];
#pragma unroll
            for (int mt = 0; mt < 2; mt++) {
                int mb = wm + mt * 16 + g;
                afr[mt][0] = As[buf][kb + c][mb];
                afr[mt][1] = As[buf][kb + c][mb + 8];
                afr[mt][2] = As[buf][kb + c + 4][mb];
                afr[mt][3] = As[buf][kb + c + 4][mb + 8];
            }
#pragma unroll
            for (int nt = 0; nt < 8; nt++) {
                int nb = wn + nt * 8 + g;
                bfr[nt][0] = Bs[buf][kb + c][nb];
                bfr[nt][1] = Bs[buf][kb + c + 4][nb];
            }
#pragma unroll
            for (int mt = 0; mt < 2; mt++)
#pragma unroll
                for (int nt = 0; nt < 8; nt++)
                    mma_tf32(acc[mt][nt], afr[mt], bfr[nt]);
        }
        __syncthreads();
        if (more) {
            storeSlab(1 - buf);
            __syncthreads();
        }
    }

    // epilogue
#pragma unroll
    for (int mt = 0; mt < 2; mt++) {
#pragma unroll
        for (int nt = 0; nt < 8; nt++) {
            const float* d = acc[mt][nt];
            int mrow = m0 + wm + mt * 16 + g;
            int ncol = n0 + wn + nt * 8 + 2 * c;
            float b0v = 0.f, b1v = 0.f;
            if (bias) { b0v = bias[ncol]; b1v = bias[ncol + 1]; }
            float v0 = d[0] + b0v, v1 = d[1] + b1v;
            float v2 = d[2] + b0v, v3 = d[3] + b1v;
            if (relu) {
                v0 = fmaxf(v0, 0.f); v1 = fmaxf(v1, 0.f);
                v2 = fmaxf(v2, 0.f); v3 = fmaxf(v3, 0.f);
            }
            if (mrow < M)     *(float2*)(C + (size_t)mrow * N + ncol)       = make_float2(v0, v1);
            if (mrow + 8 < M) *(float2*)(C + (size_t)(mrow + 8) * N + ncol) = make_float2(v2, v3);
        }
    }
}

// ---------------- bias combine ----------------
__global__ __launch_bounds__(256) void bias2_kernel(const float* a, const float* b, float* o, int n) {
    int i = blockIdx.x * blockDim.x + threadIdx.x;
    if (i < n) o[i] = a[i] + b[i];
}

// ---------------- LSTM recurrence, coalesced transposed weights ----------------
// 32 CTAs x 128 threads, 2 batches per CTA. Thread q owns gates 4q..4q+3.
// WhhT layout: [k 0..127][j 0..511] so the k-loop load is a coalesced float4.
__global__ __launch_bounds__(128) void lstm_rec_kernel(
                                const float* __restrict__ gx,    // B*T*512, x@Wih^T + bih + bhh
                                const float* __restrict__ WhhT,  // [128][512]
                                float* __restrict__ hout) {      // B*T*128
    int b0 = blockIdx.x * 2;
    int q = threadIdx.x;  // 0..127
    __shared__ float sh_h[2][HH];
    __shared__ float sh_g[2][4 * HH];
    float c0 = 0.0f, c1 = 0.0f;
    sh_h[0][q] = 0.0f; sh_h[1][q] = 0.0f;
    __syncthreads();
    const float4* WT4 = (const float4*)WhhT;   // [k][128 float4], entry = WhhT[k][4q..4q+3]
    for (int t = 0; t < TT; t++) {
        float4 ga = *(const float4*)(gx + ((size_t)b0 * TT + t) * 512 + 4 * q);
        float4 gb = *(const float4*)(gx + ((size_t)(b0 + 1) * TT + t) * 512 + 4 * q);
        float a0 = ga.x, a1 = ga.y, a2 = ga.z, a3 = ga.w;
        float e0 = gb.x, e1 = gb.y, e2 = gb.z, e3 = gb.w;
#pragma unroll 8
        for (int k = 0; k < HH; k++) {
            float4 w = WT4[k * 128 + q];
            float h0 = sh_h[0][k];
            float h1 = sh_h[1][k];
            a0 += w.x * h0; a1 += w.y * h0; a2 += w.z * h0; a3 += w.w * h0;
            e0 += w.x * h1; e1 += w.y * h1; e2 += w.z * h1; e3 += w.w * h1;
        }
        *(float4*)&sh_g[0][4 * q] = make_float4(a0, a1, a2, a3);
        *(float4*)&sh_g[1][4 * q] = make_float4(e0, e1, e2, e3);
        __syncthreads();
        {
            float gi = sh_g[0][q], gf = sh_g[0][HH + q], gg = sh_g[0][2 * HH + q], go = sh_g[0][3 * HH + q];
            c0 = sigf(gf) * c0 + sigf(gi) * tanhf(gg);
            float h = sigf(go) * tanhf(c0);
            sh_h[0][q] = h;
            hout[((size_t)b0 * TT + t) * HH + q] = h;
        }
        {
            float gi = sh_g[1][q], gf = sh_g[1][HH + q], gg = sh_g[1][2 * HH + q], go = sh_g[1][3 * HH + q];
            c1 = sigf(gf) * c1 + sigf(gi) * tanhf(gg);
            float h = sigf(go) * tanhf(c1);
            sh_h[1][q] = h;
            hout[((size_t)(b0 + 1) * TT + t) * HH + q] = h;
        }
        __syncthreads();
    }
}

// ---------------- attention: only last query row needed ----------------
__global__ __launch_bounds__(256) void attn_last_kernel(const float* __restrict__ qkv, float* __restrict__ olast) {
    int gidx = blockIdx.x * blockDim.x + threadIdx.x;
    int w = gidx >> 5;                // 0..127 : (b, head)
    if (w >= BB * 2) return;
    int lane = threadIdx.x & 31;
    int wl = threadIdx.x >> 5;
    int b = w >> 1, h = w & 1;
    const float* base = qkv + (size_t)b * TT * 384;
    const float* q = base + 49 * 384 + h * 64;
    float q0 = q[lane], q1 = q[lane + 32];
    __shared__ float sc[8][TT];
    for (int j = 0; j < TT; j++) {
        const float* kp = base + j * 384 + 128 + h * 64;
        float p = q0 * kp[lane] + q1 * kp[lane + 32];
#pragma unroll
        for (int o = 16; o; o >>= 1) p += __shfl_down_sync(0xffffffffu, p, o);
        if (lane == 0) sc[wl][j] = p * 0.125f;   // /sqrt(64)
    }
    __syncwarp();
    float v0 = (lane < TT) ? sc[wl][lane] : -1e30f;
    float v1 = (lane + 32 < TT) ? sc[wl][lane + 32] : -1e30f;
    float mx = fmaxf(v0, v1);
#pragma unroll
    for (int o = 16; o; o >>= 1) mx = fmaxf(mx, __shfl_xor_sync(0xffffffffu, mx, o));
    float e0 = (lane < TT) ? expf(v0 - mx) : 0.f;
    float e1 = (lane + 32 < TT) ? expf(v1 - mx) : 0.f;
    float s = e0 + e1;
#pragma unroll
    for (int o = 16; o; o >>= 1) s += __shfl_xor_sync(0xffffffffu, s, o);
    float inv = 1.0f / s;
    if (lane < TT) sc[wl][lane] = e0 * inv;
    if (lane + 32 < TT) sc[wl][lane + 32] = e1 * inv;
    __syncwarp();
    float a0 = 0.f, a1 = 0.f;
    for (int j = 0; j < TT; j++) {
        float wj = sc[wl][j];
        const float* vp = base + j * 384 + 256 + h * 64;
        a0 += wj * vp[lane];
        a1 += wj * vp[lane + 32];
    }
    olast[b * HH + h * 64 + lane] = a0;
    olast[b * HH + h * 64 + lane + 32] = a1;
}

// ---------------- final: out-proj (last row) + MLP head ----------------
__global__ __launch_bounds__(128) void head_kernel(const float* __restrict__ olast,
                            const float* __restrict__ Wout, const float* __restrict__ bout,
                            const float* __restrict__ W1, const float* __restrict__ b1,
                            const float* __restrict__ W2, const float* __restrict__ b2,
                            float* __restrict__ pred) {
    int b = blockIdx.x;
    int j = threadIdx.x;  // 128
    __shared__ float o[HH], a[HH], hid[64];
    o[j] = olast[b * HH + j];
    __syncthreads();
    {
        float acc = bout[j];
        const float* w = Wout + (size_t)j * HH;
#pragma unroll 4
        for (int k = 0; k < HH; k++) acc += o[k] * w[k];
        a[j] = acc;
    }
    __syncthreads();
    if (j < 64) {
        float acc = b1[j];
        const float* w = W1 + (size_t)j * HH;
#pragma unroll 4
        for (int k = 0; k < HH; k++) acc += a[k] * w[k];
        hid[j] = fmaxf(acc, 0.0f);
    }
    __syncthreads();
    if (j == 0) {
        float p = b2[0];
#pragma unroll
        for (int k = 0; k < 64; k++) p += hid[k] * W2[k];
        pred[b] = p;
    }
}

// ---------------- host launch ----------------
extern "C" void kernel_launch(void* const* d_in, const int* in_sizes, int n_in,
                              void* d_out, int out_size) {
    (void)in_sizes; (void)n_in; (void)out_size;
    const float* x     = (const float*)d_in[0];
    const int*   eidx  = (const int*)d_in[1];
    const float* tseq  = (const float*)d_in[2];
    const float* W_red = (const float*)d_in[3];
    const float* b_red = (const float*)d_in[4];
    const float* s1Wl  = (const float*)d_in[5];
    const float* s1bl  = (const float*)d_in[6];
    const float* s1Wr  = (const float*)d_in[7];
    const float* s2Wl  = (const float*)d_in[8];
    const float* s2bl  = (const float*)d_in[9];
    const float* s2Wr  = (const float*)d_in[10];
    const float* Wih0  = (const float*)d_in[11];
    const float* Whh0  = (const float*)d_in[12];
    const float* bih0  = (const float*)d_in[13];
    const float* bhh0  = (const float*)d_in[14];
    const float* Wih1  = (const float*)d_in[15];
    const float* Whh1  = (const float*)d_in[16];
    const float* bih1  = (const float*)d_in[17];
    const float* bhh1  = (const float*)d_in[18];
    const float* Win   = (const float*)d_in[19];
    const float* binp  = (const float*)d_in[20];
    const float* Wout  = (const float*)d_in[21];
    const float* bout  = (const float*)d_in[22];
    const float* hW1   = (const float*)d_in[23];
    const float* hb1   = (const float*)d_in[24];
    const float* hW2   = (const float*)d_in[25];
    const float* hb2   = (const float*)d_in[26];

    float* out     = (float*)d_out;
    float* pred    = out;        // (64,1)
    float* spatial = out + BB;   // (50000,128)

    const int* src = eidx;
    const int* dst = eidx + EE;

    void* p;
    cudaGetSymbolAddress(&p, g_reduced); float* reduced = (float*)p;
    cudaGetSymbolAddress(&p, g_agg);     float* agg     = (float*)p;
    cudaGetSymbolAddress(&p, g_s);       float* sbuf    = (float*)p;
    cudaGetSymbolAddress(&p, g_invdeg);  float* invdeg  = (float*)p;
    cudaGetSymbolAddress(&p, g_deg);     int*   deg     = (int*)p;
    cudaGetSymbolAddress(&p, g_ts);      float* ts      = (float*)p;
    cudaGetSymbolAddress(&p, g_gates);   float* gates   = (float*)p;
    cudaGetSymbolAddress(&p, g_h1);      float* h1      = (float*)p;
    cudaGetSymbolAddress(&p, g_h2);      float* h2      = (float*)p;
    cudaGetSymbolAddress(&p, g_qkv);     float* qkv     = (float*)p;
    cudaGetSymbolAddress(&p, g_olast);   float* olast   = (float*)p;
    cudaGetSymbolAddress(&p, g_bias0);   float* bias0   = (float*)p;
    cudaGetSymbolAddress(&p, g_bias1);   float* bias1   = (float*)p;
    cudaGetSymbolAddress(&p, g_WhhT0);   float* WhhT0   = (float*)p;
    cudaGetSymbolAddress(&p, g_WhhT1);   float* WhhT1   = (float*)p;

    // Launch order chosen so ncu (-s 5 -c 1) profiles launch #6 = big tf32 GEMM.
    cudaMemsetAsync(agg, 0, sizeof(float) * (size_t)NND * HH);           // 1
    cudaMemsetAsync(deg, 0, sizeof(int) * NND);                           // 2
    bias2_kernel<<<2, 256>>>(bih0, bhh0, bias0, 4 * HH);                  // 3
    bias2_kernel<<<2, 256>>>(bih1, bhh1, bias1, 4 * HH);                  // 4
    transposeW_kernel<<<256, 256>>>(Whh0, Whh1, WhhT0, WhhT1);            // 5

    // 6: reduced = x @ W_red^T + b_red   <-- PROFILED
    gemm_tf32_kernel<<<dim3((NND + 127) / 128, HH / 128), 256>>>(
        x, W_red, x, W_red, nullptr, b_red, reduced, NND, HH, FF, FF, 0);

    deg_kernel<<<(EE + 255) / 256, 256>>>(dst, deg, EE);                  // 7
    invdeg_kernel<<<(NND + 255) / 256, 256>>>(deg, invdeg, NND);          // 8

    // 9: agg += reduced[src] scattered to dst
    {
        long long tot = (long long)EE * 32;
        scatter_add_kernel<<<(unsigned)((tot + 255) / 256), 256>>>(reduced, src, dst, agg, EE);
    }

    // 10: ts = time_sequence @ W_red^T + b_red   (3200 x 128)
    gemm_tf32_kernel<<<dim3((BB * TT + 127) / 128, HH / 128), 256>>>(
        tseq, W_red, tseq, W_red, nullptr, b_red, ts, BB * TT, HH, FF, FF, 0);

    // 11: s = relu((agg*invdeg) @ Wl1^T + bl1 + reduced @ Wr1^T)
    gemm_tf32_kernel<<<dim3((NND + 127) / 128, HH / 128), 256>>>(
        agg, s1Wl, reduced, s1Wr, invdeg, s1bl, sbuf, NND, HH, 2 * HH, HH, 1);

    cudaMemsetAsync(agg, 0, sizeof(float) * (size_t)NND * HH);            // 12
    {
        long long tot = (long long)EE * 32;                               // 13
        scatter_add_kernel<<<(unsigned)((tot + 255) / 256), 256>>>(sbuf, src, dst, agg, EE);
    }
    // 14: spatial = relu((agg*invdeg) @ Wl2^T + bl2 + s @ Wr2^T)
    gemm_tf32_kernel<<<dim3((NND + 127) / 128, HH / 128), 256>>>(
        agg, s2Wl, sbuf, s2Wr, invdeg, s2bl, spatial, NND, HH, 2 * HH, HH, 1);

    // ---- temporal branch ----
    // 15: gates0 = ts @ Wih0^T + (bih0+bhh0)
    gemm_tf32_kernel<<<dim3((BB * TT + 127) / 128, (4 * HH) / 128), 256>>>(
        ts, Wih0, ts, Wih0, nullptr, bias0, gates, BB * TT, 4 * HH, HH, HH, 0);
    lstm_rec_kernel<<<BB / 2, 128>>>(gates, WhhT0, h1);                   // 16

    // 17: gates1 = h1 @ Wih1^T + (bih1+bhh1)
    gemm_tf32_kernel<<<dim3((BB * TT + 127) / 128, (4 * HH) / 128), 256>>>(
        h1, Wih1, h1, Wih1, nullptr, bias1, gates, BB * TT, 4 * HH, HH, HH, 0);
    lstm_rec_kernel<<<BB / 2, 128>>>(gates, WhhT1, h2);                   // 18

    // 19: qkv = h2 @ Win^T + bin   (3200 x 384)
    gemm_tf32_kernel<<<dim3((BB * TT + 127) / 128, (3 * HH) / 128), 256>>>(
        h2, Win, h2, Win, nullptr, binp, qkv, BB * TT, 3 * HH, HH, HH, 0);

    attn_last_kernel<<<16, 256>>>(qkv, olast);                            // 20
    head_kernel<<<BB, HH>>>(olast, Wout, bout, hW1, hb1, hW2, hb2, pred); // 21
}

// round 7
// speedup vs baseline: 1.3896x; 1.2286x over previous
#include <cuda_runtime.h>
#include <cuda_bf16.h>
#include <math.h>
#include <stdint.h>

// Problem constants
#define NND 50000
#define FF  256
#define HH  128
#define EE  800000
#define BB  64
#define TT  50

// ---------------- device scratch ----------------
__device__ float g_reduced[NND * HH];
__device__ float g_agg[NND * HH];
__device__ float g_s[NND * HH];
__device__ float g_invdeg[NND];
__device__ int   g_deg[NND];
__device__ float g_ts[BB * TT * HH];
__device__ float g_gates[BB * TT * 4 * HH];
__device__ float g_h1[BB * TT * HH];
__device__ float g_h2[BB * TT * HH];
__device__ float g_qkv[BB * TT * 3 * HH];
__device__ float g_olast[BB * HH];
__device__ float g_bias0[4 * HH];
__device__ float g_bias1[4 * HH];
__device__ float g_WhhT0[HH * 4 * HH];   // [128][512] transposed Whh0
__device__ float g_WhhT1[HH * 4 * HH];   // [128][512] transposed Whh1

__device__ __forceinline__ float sigf(float x) { return 1.0f / (1.0f + __expf(-x)); }

__device__ __forceinline__ uint32_t f2tf32(float f) {
    uint32_t u;
    asm("cvt.rna.tf32.f32 %0, %1;" : "=r"(u) : "f"(f));
    return u;
}

__device__ __forceinline__ void mma_tf32(float* d, const uint32_t* a, const uint32_t* b) {
    asm volatile("mma.sync.aligned.m16n8k8.row.col.f32.tf32.tf32.f32 "
                 "{%0,%1,%2,%3}, {%4,%5,%6,%7}, {%8,%9}, {%0,%1,%2,%3};"
                 : "+f"(d[0]), "+f"(d[1]), "+f"(d[2]), "+f"(d[3])
                 : "r"(a[0]), "r"(a[1]), "r"(a[2]), "r"(a[3]), "r"(b[0]), "r"(b[1]));
}

// ---------------- degree kernels ----------------
__global__ __launch_bounds__(256) void deg_kernel(const int* __restrict__ dst, int* __restrict__ deg, int E) {
    int i = blockIdx.x * blockDim.x + threadIdx.x;
    if (i < E) atomicAdd(&deg[dst[i]], 1);
}

__global__ __launch_bounds__(256) void invdeg_kernel(const int* __restrict__ deg, float* __restrict__ inv, int n) {
    int i = blockIdx.x * blockDim.x + threadIdx.x;
    if (i < n) inv[i] = 1.0f / (float)max(deg[i], 1);
}

// ---------------- weight transpose: Whh[512][128] -> WhhT[128][512] ----------------
__global__ __launch_bounds__(256) void transposeW_kernel(const float* __restrict__ W0,
                                                         const float* __restrict__ W1,
                                                         float* __restrict__ T0,
                                                         float* __restrict__ T1) {
    int idx = blockIdx.x * blockDim.x + threadIdx.x;
    if (idx < 512 * 128) {
        int j = idx >> 7;      // gate row 0..511
        int k = idx & 127;     // hidden col 0..127
        T0[k * 512 + j] = W0[idx];
        T1[k * 512 + j] = W1[idx];
    }
}

// ---------------- scatter-add (one warp per edge, v4 reductions) ----------------
__global__ __launch_bounds__(256) void scatter_add_kernel(const float* __restrict__ feat,
                                   const int* __restrict__ src,
                                   const int* __restrict__ dst,
                                   float* __restrict__ agg, int E) {
    int idx = blockIdx.x * blockDim.x + threadIdx.x;
    int e = idx >> 5;
    if (e >= E) return;
    int lane = idx & 31;
    int s = __ldg(src + e);
    int d = __ldg(dst + e);
    float4 v = *(const float4*)(feat + (size_t)s * HH + lane * 4);
    float* p = agg + (size_t)d * HH + lane * 4;
    asm volatile("red.global.add.v4.f32 [%0], {%1,%2,%3,%4};"
                 :: "l"(p), "f"(v.x), "f"(v.y), "f"(v.z), "f"(v.w) : "memory");
}

// ---------------- tf32 tensor-core NT GEMM ----------------
// C(MxN) = A1(MxKsplit)@B1(NxKsplit)^T + A2(Mx(Ktot-Ksplit))@B2(Nx..)^T + bias, opt relu.
// Rows of A1 optionally scaled by rowscale[m]. N multiple of 128, Ktot & Ksplit multiples of 16.
#define KT 16
__global__ __launch_bounds__(256) void gemm_tf32_kernel(
        const float* __restrict__ A1, const float* __restrict__ B1,
        const float* __restrict__ A2, const float* __restrict__ B2,
        const float* __restrict__ rowscale,
        const float* __restrict__ bias,
        float* __restrict__ C,
        int M, int N, int Ktot, int Ksplit, int relu) {
    __shared__ uint32_t As[2][KT][136];
    __shared__ uint32_t Bs[2][KT][136];
    const int tid  = threadIdx.x;
    const int m0   = blockIdx.x * 128;
    const int n0   = blockIdx.y * 128;
    const int warp = tid >> 5, lane = tid & 31;
    const int wm   = (warp >> 1) * 32;   // 4 warps in m
    const int wn   = (warp & 1) * 64;    // 2 warps in n
    const int g    = lane >> 2, c = lane & 3;
    const bool haveScale = (rowscale != nullptr);

    float acc[2][8][4];
#pragma unroll
    for (int mt = 0; mt < 2; mt++)
#pragma unroll
        for (int nt = 0; nt < 8; nt++)
#pragma unroll
            for (int r = 0; r < 4; r++) acc[mt][nt][r] = 0.0f;

    const int numSlabs = Ktot / KT;

    const int row0 = tid & 127, kc0 = tid >> 7;          // kc0 in {0,1}
    const int row1 = tid & 127, kc1 = (tid >> 7) + 2;    // {2,3}

    float4 pa[2], pb[2];

    auto loadSlab = [&](int s) {
        int kbase = s * KT;
        const float* A; const float* Bm; int lda, koff; bool sc;
        if (kbase < Ksplit) { A = A1; Bm = B1; lda = Ksplit;        koff = kbase;          sc = haveScale; }
        else                { A = A2; Bm = B2; lda = Ktot - Ksplit; koff = kbase - Ksplit; sc = false; }
        {
            int m = m0 + row0;
            pa[0] = make_float4(0.f, 0.f, 0.f, 0.f);
            if (m < M) {
                pa[0] = *(const float4*)(A + (size_t)m * lda + koff + kc0 * 4);
                if (sc) { float sv = rowscale[m]; pa[0].x *= sv; pa[0].y *= sv; pa[0].z *= sv; pa[0].w *= sv; }
            }
            pb[0] = *(const float4*)(Bm + (size_t)(n0 + row0) * lda + koff + kc0 * 4);
        }
        {
            int m = m0 + row1;
            pa[1] = make_float4(0.f, 0.f, 0.f, 0.f);
            if (m < M) {
                pa[1] = *(const float4*)(A + (size_t)m * lda + koff + kc1 * 4);
                if (sc) { float sv = rowscale[m]; pa[1].x *= sv; pa[1].y *= sv; pa[1].z *= sv; pa[1].w *= sv; }
            }
            pb[1] = *(const float4*)(Bm + (size_t)(n0 + row1) * lda + koff + kc1 * 4);
        }
    };

    auto storeSlab = [&](int buf) {
        int k0 = kc0 * 4;
        As[buf][k0 + 0][row0] = f2tf32(pa[0].x); As[buf][k0 + 1][row0] = f2tf32(pa[0].y);
        As[buf][k0 + 2][row0] = f2tf32(pa[0].z); As[buf][k0 + 3][row0] = f2tf32(pa[0].w);
        Bs[buf][k0 + 0][row0] = f2tf32(pb[0].x); Bs[buf][k0 + 1][row0] = f2tf32(pb[0].y);
        Bs[buf][k0 + 2][row0] = f2tf32(pb[0].z); Bs[buf][k0 + 3][row0] = f2tf32(pb[0].w);
        int k1 = kc1 * 4;
        As[buf][k1 + 0][row1] = f2tf32(pa[1].x); As[buf][k1 + 1][row1] = f2tf32(pa[1].y);
        As[buf][k1 + 2][row1] = f2tf32(pa[1].z); As[buf][k1 + 3][row1] = f2tf32(pa[1].w);
        Bs[buf][k1 + 0][row1] = f2tf32(pb[1].x); Bs[buf][k1 + 1][row1] = f2tf32(pb[1].y);
        Bs[buf][k1 + 2][row1] = f2tf32(pb[1].z); Bs[buf][k1 + 3][row1] = f2tf32(pb[1].w);
    };

    loadSlab(0);
    storeSlab(0);
    __syncthreads();

    for (int s = 0; s < numSlabs; s++) {
        int buf = s & 1;
        bool more = (s + 1) < numSlabs;
        if (more) loadSlab(s + 1);
#pragma unroll
        for (int k8 = 0; k8 < 2; k8++) {
            int kb = k8 * 8;
            uint32_t afr[2][4], bfr[8][2];
#pragma unroll
            for (int mt = 0; mt < 2; mt++) {
                int mb = wm + mt * 16 + g;
                afr[mt][0] = As[buf][kb + c][mb];
                afr[mt][1] = As[buf][kb + c][mb + 8];
                afr[mt][2] = As[buf][kb + c + 4][mb];
                afr[mt][3] = As[buf][kb + c + 4][mb + 8];
            }
#pragma unroll
            for (int nt = 0; nt < 8; nt++) {
                int nb = wn + nt * 8 + g;
                bfr[nt][0] = Bs[buf][kb + c][nb];
                bfr[nt][1] = Bs[buf][kb + c + 4][nb];
            }
#pragma unroll
            for (int mt = 0; mt < 2; mt++)
#pragma unroll
                for (int nt = 0; nt < 8; nt++)
                    mma_tf32(acc[mt][nt], afr[mt], bfr[nt]);
        }
        __syncthreads();
        if (more) {
            storeSlab(1 - buf);
            __syncthreads();
        }
    }

    // epilogue
#pragma unroll
    for (int mt = 0; mt < 2; mt++) {
#pragma unroll
        for (int nt = 0; nt < 8; nt++) {
            const float* d = acc[mt][nt];
            int mrow = m0 + wm + mt * 16 + g;
            int ncol = n0 + wn + nt * 8 + 2 * c;
            float b0v = 0.f, b1v = 0.f;
            if (bias) { b0v = bias[ncol]; b1v = bias[ncol + 1]; }
            float v0 = d[0] + b0v, v1 = d[1] + b1v;
            float v2 = d[2] + b0v, v3 = d[3] + b1v;
            if (relu) {
                v0 = fmaxf(v0, 0.f); v1 = fmaxf(v1, 0.f);
                v2 = fmaxf(v2, 0.f); v3 = fmaxf(v3, 0.f);
            }
            if (mrow < M)     *(float2*)(C + (size_t)mrow * N + ncol)       = make_float2(v0, v1);
            if (mrow + 8 < M) *(float2*)(C + (size_t)(mrow + 8) * N + ncol) = make_float2(v2, v3);
        }
    }
}

// ---------------- bias combine ----------------
__global__ __launch_bounds__(256) void bias2_kernel(const float* a, const float* b, float* o, int n) {
    int i = blockIdx.x * blockDim.x + threadIdx.x;
    if (i < n) o[i] = a[i] + b[i];
}

// ---------------- LSTM recurrence, explicit MLP=16 weight prefetch ----------------
// 32 CTAs x 128 threads, 2 batches per CTA. Thread q owns gate-quad 4q..4q+3.
// WhhT layout: [k 0..127][j 0..511]; load WT4[k*128+q] = coalesced 512B per warp.
__global__ __launch_bounds__(128) void lstm_rec_kernel(
                                const float* __restrict__ gx,    // B*T*512, x@Wih^T + bih + bhh
                                const float* __restrict__ WhhT,  // [128][512]
                                float* __restrict__ hout) {      // B*T*128
    int b0 = blockIdx.x * 2;
    int q = threadIdx.x;  // 0..127
    __shared__ float sh_h[2][HH];
    __shared__ float sh_g[2][4 * HH];
    float c0 = 0.0f, c1 = 0.0f;
    sh_h[0][q] = 0.0f; sh_h[1][q] = 0.0f;
    __syncthreads();
    const float4* __restrict__ WT4 = (const float4*)WhhT;   // [k][128 float4]
    for (int t = 0; t < TT; t++) {
        float4 ga = *(const float4*)(gx + ((size_t)b0 * TT + t) * 512 + 4 * q);
        float4 gb = *(const float4*)(gx + ((size_t)(b0 + 1) * TT + t) * 512 + 4 * q);
        float a0 = ga.x, a1 = ga.y, a2 = ga.z, a3 = ga.w;
        float e0 = gb.x, e1 = gb.y, e2 = gb.z, e3 = gb.w;
#pragma unroll
        for (int kc = 0; kc < HH; kc += 16) {
            float4 w[16];
#pragma unroll
            for (int i = 0; i < 16; i++)
                w[i] = __ldg(&WT4[(kc + i) * 128 + q]);
#pragma unroll
            for (int i = 0; i < 16; i++) {
                float h0 = sh_h[0][kc + i];
                float h1 = sh_h[1][kc + i];
                a0 += w[i].x * h0; a1 += w[i].y * h0; a2 += w[i].z * h0; a3 += w[i].w * h0;
                e0 += w[i].x * h1; e1 += w[i].y * h1; e2 += w[i].z * h1; e3 += w[i].w * h1;
            }
        }
        *(float4*)&sh_g[0][4 * q] = make_float4(a0, a1, a2, a3);
        *(float4*)&sh_g[1][4 * q] = make_float4(e0, e1, e2, e3);
        __syncthreads();
        {
            float gi = sh_g[0][q], gf = sh_g[0][HH + q], gg = sh_g[0][2 * HH + q], go = sh_g[0][3 * HH + q];
            c0 = sigf(gf) * c0 + sigf(gi) * tanhf(gg);
            float h = sigf(go) * tanhf(c0);
            sh_h[0][q] = h;
            hout[((size_t)b0 * TT + t) * HH + q] = h;
        }
        {
            float gi = sh_g[1][q], gf = sh_g[1][HH + q], gg = sh_g[1][2 * HH + q], go = sh_g[1][3 * HH + q];
            c1 = sigf(gf) * c1 + sigf(gi) * tanhf(gg);
            float h = sigf(go) * tanhf(c1);
            sh_h[1][q] = h;
            hout[((size_t)(b0 + 1) * TT + t) * HH + q] = h;
        }
        __syncthreads();
    }
}

// ---------------- attention: only last query row needed ----------------
__global__ __launch_bounds__(256) void attn_last_kernel(const float* __restrict__ qkv, float* __restrict__ olast) {
    int gidx = blockIdx.x * blockDim.x + threadIdx.x;
    int w = gidx >> 5;                // 0..127 : (b, head)
    if (w >= BB * 2) return;
    int lane = threadIdx.x & 31;
    int wl = threadIdx.x >> 5;
    int b = w >> 1, h = w & 1;
    const float* base = qkv + (size_t)b * TT * 384;
    const float* q = base + 49 * 384 + h * 64;
    float q0 = q[lane], q1 = q[lane + 32];
    __shared__ float sc[8][TT];
    for (int j = 0; j < TT; j++) {
        const float* kp = base + j * 384 + 128 + h * 64;
        float p = q0 * kp[lane] + q1 * kp[lane + 32];
#pragma unroll
        for (int o = 16; o; o >>= 1) p += __shfl_down_sync(0xffffffffu, p, o);
        if (lane == 0) sc[wl][j] = p * 0.125f;   // /sqrt(64)
    }
    __syncwarp();
    float v0 = (lane < TT) ? sc[wl][lane] : -1e30f;
    float v1 = (lane + 32 < TT) ? sc[wl][lane + 32] : -1e30f;
    float mx = fmaxf(v0, v1);
#pragma unroll
    for (int o = 16; o; o >>= 1) mx = fmaxf(mx, __shfl_xor_sync(0xffffffffu, mx, o));
    float e0 = (lane < TT) ? expf(v0 - mx) : 0.f;
    float e1 = (lane + 32 < TT) ? expf(v1 - mx) : 0.f;
    float s = e0 + e1;
#pragma unroll
    for (int o = 16; o; o >>= 1) s += __shfl_xor_sync(0xffffffffu, s, o);
    float inv = 1.0f / s;
    if (lane < TT) sc[wl][lane] = e0 * inv;
    if (lane + 32 < TT) sc[wl][lane + 32] = e1 * inv;
    __syncwarp();
    float a0 = 0.f, a1 = 0.f;
    for (int j = 0; j < TT; j++) {
        float wj = sc[wl][j];
        const float* vp = base + j * 384 + 256 + h * 64;
        a0 += wj * vp[lane];
        a1 += wj * vp[lane + 32];
    }
    olast[b * HH + h * 64 + lane] = a0;
    olast[b * HH + h * 64 + lane + 32] = a1;
}

// ---------------- final: out-proj (last row) + MLP head ----------------
__global__ __launch_bounds__(128) void head_kernel(const float* __restrict__ olast,
                            const float* __restrict__ Wout, const float* __restrict__ bout,
                            const float* __restrict__ W1, const float* __restrict__ b1,
                            const float* __restrict__ W2, const float* __restrict__ b2,
                            float* __restrict__ pred) {
    int b = blockIdx.x;
    int j = threadIdx.x;  // 128
    __shared__ float o[HH], a[HH], hid[64];
    o[j] = olast[b * HH + j];
    __syncthreads();
    {
        float acc = bout[j];
        const float* w = Wout + (size_t)j * HH;
#pragma unroll 4
        for (int k = 0; k < HH; k++) acc += o[k] * w[k];
        a[j] = acc;
    }
    __syncthreads();
    if (j < 64) {
        float acc = b1[j];
        const float* w = W1 + (size_t)j * HH;
#pragma unroll 4
        for (int k = 0; k < HH; k++) acc += a[k] * w[k];
        hid[j] = fmaxf(acc, 0.0f);
    }
    __syncthreads();
    if (j == 0) {
        float p = b2[0];
#pragma unroll
        for (int k = 0; k < 64; k++) p += hid[k] * W2[k];
        pred[b] = p;
    }
}

// ---------------- host launch ----------------
extern "C" void kernel_launch(void* const* d_in, const int* in_sizes, int n_in,
                              void* d_out, int out_size) {
    (void)in_sizes; (void)n_in; (void)out_size;
    const float* x     = (const float*)d_in[0];
    const int*   eidx  = (const int*)d_in[1];
    const float* tseq  = (const float*)d_in[2];
    const float* W_red = (const float*)d_in[3];
    const float* b_red = (const float*)d_in[4];
    const float* s1Wl  = (const float*)d_in[5];
    const float* s1bl  = (const float*)d_in[6];
    const float* s1Wr  = (const float*)d_in[7];
    const float* s2Wl  = (const float*)d_in[8];
    const float* s2bl  = (const float*)d_in[9];
    const float* s2Wr  = (const float*)d_in[10];
    const float* Wih0  = (const float*)d_in[11];
    const float* Whh0  = (const float*)d_in[12];
    const float* bih0  = (const float*)d_in[13];
    const float* bhh0  = (const float*)d_in[14];
    const float* Wih1  = (const float*)d_in[15];
    const float* Whh1  = (const float*)d_in[16];
    const float* bih1  = (const float*)d_in[17];
    const float* bhh1  = (const float*)d_in[18];
    const float* Win   = (const float*)d_in[19];
    const float* binp  = (const float*)d_in[20];
    const float* Wout  = (const float*)d_in[21];
    const float* bout  = (const float*)d_in[22];
    const float* hW1   = (const float*)d_in[23];
    const float* hb1   = (const float*)d_in[24];
    const float* hW2   = (const float*)d_in[25];
    const float* hb2   = (const float*)d_in[26];

    float* out     = (float*)d_out;
    float* pred    = out;        // (64,1)
    float* spatial = out + BB;   // (50000,128)

    const int* src = eidx;
    const int* dst = eidx + EE;

    void* p;
    cudaGetSymbolAddress(&p, g_reduced); float* reduced = (float*)p;
    cudaGetSymbolAddress(&p, g_agg);     float* agg     = (float*)p;
    cudaGetSymbolAddress(&p, g_s);       float* sbuf    = (float*)p;
    cudaGetSymbolAddress(&p, g_invdeg);  float* invdeg  = (float*)p;
    cudaGetSymbolAddress(&p, g_deg);     int*   deg     = (int*)p;
    cudaGetSymbolAddress(&p, g_ts);      float* ts      = (float*)p;
    cudaGetSymbolAddress(&p, g_gates);   float* gates   = (float*)p;
    cudaGetSymbolAddress(&p, g_h1);      float* h1      = (float*)p;
    cudaGetSymbolAddress(&p, g_h2);      float* h2      = (float*)p;
    cudaGetSymbolAddress(&p, g_qkv);     float* qkv     = (float*)p;
    cudaGetSymbolAddress(&p, g_olast);   float* olast   = (float*)p;
    cudaGetSymbolAddress(&p, g_bias0);   float* bias0   = (float*)p;
    cudaGetSymbolAddress(&p, g_bias1);   float* bias1   = (float*)p;
    cudaGetSymbolAddress(&p, g_WhhT0);   float* WhhT0   = (float*)p;
    cudaGetSymbolAddress(&p, g_WhhT1);   float* WhhT1   = (float*)p;

    // Launch order: ncu (-s 5 -c 1) profiles launch #6 = lstm_rec layer 0.
    bias2_kernel<<<2, 256>>>(bih0, bhh0, bias0, 4 * HH);                  // 1
    bias2_kernel<<<2, 256>>>(bih1, bhh1, bias1, 4 * HH);                  // 2
    transposeW_kernel<<<256, 256>>>(Whh0, Whh1, WhhT0, WhhT1);            // 3

    // 4: ts = time_sequence @ W_red^T + b_red   (3200 x 128)
    gemm_tf32_kernel<<<dim3((BB * TT + 127) / 128, HH / 128), 256>>>(
        tseq, W_red, tseq, W_red, nullptr, b_red, ts, BB * TT, HH, FF, FF, 0);

    // 5: gates0 = ts @ Wih0^T + (bih0+bhh0)
    gemm_tf32_kernel<<<dim3((BB * TT + 127) / 128, (4 * HH) / 128), 256>>>(
        ts, Wih0, ts, Wih0, nullptr, bias0, gates, BB * TT, 4 * HH, HH, HH, 0);

    // 6: LSTM layer 0   <-- PROFILED
    lstm_rec_kernel<<<BB / 2, 128>>>(gates, WhhT0, h1);

    cudaMemsetAsync(agg, 0, sizeof(float) * (size_t)NND * HH);            // 7
    cudaMemsetAsync(deg, 0, sizeof(int) * NND);                           // 8
    deg_kernel<<<(EE + 255) / 256, 256>>>(dst, deg, EE);                  // 9
    invdeg_kernel<<<(NND + 255) / 256, 256>>>(deg, invdeg, NND);          // 10

    // 11: reduced = x @ W_red^T + b_red
    gemm_tf32_kernel<<<dim3((NND + 127) / 128, HH / 128), 256>>>(
        x, W_red, x, W_red, nullptr, b_red, reduced, NND, HH, FF, FF, 0);

    // 12: agg += reduced[src] scattered to dst
    {
        long long tot = (long long)EE * 32;
        scatter_add_kernel<<<(unsigned)((tot + 255) / 256), 256>>>(reduced, src, dst, agg, EE);
    }

    // 13: s = relu((agg*invdeg) @ Wl1^T + bl1 + reduced @ Wr1^T)
    gemm_tf32_kernel<<<dim3((NND + 127) / 128, HH / 128), 256>>>(
        agg, s1Wl, reduced, s1Wr, invdeg, s1bl, sbuf, NND, HH, 2 * HH, HH, 1);

    cudaMemsetAsync(agg, 0, sizeof(float) * (size_t)NND * HH);            // 14
    {
        long long tot = (long long)EE * 32;                               // 15
        scatter_add_kernel<<<(unsigned)((tot + 255) / 256), 256>>>(sbuf, src, dst, agg, EE);
    }
    // 16: spatial = relu((agg*invdeg) @ Wl2^T + bl2 + s @ Wr2^T)
    gemm_tf32_kernel<<<dim3((NND + 127) / 128, HH / 128), 256>>>(
        agg, s2Wl, sbuf, s2Wr, invdeg, s2bl, spatial, NND, HH, 2 * HH, HH, 1);

    // 17: gates1 = h1 @ Wih1^T + (bih1+bhh1)
    gemm_tf32_kernel<<<dim3((BB * TT + 127) / 128, (4 * HH) / 128), 256>>>(
        h1, Wih1, h1, Wih1, nullptr, bias1, gates, BB * TT, 4 * HH, HH, HH, 0);
    lstm_rec_kernel<<<BB / 2, 128>>>(gates, WhhT1, h2);                   // 18

    // 19: qkv = h2 @ Win^T + bin   (3200 x 384)
    gemm_tf32_kernel<<<dim3((BB * TT + 127) / 128, (3 * HH) / 128), 256>>>(
        h2, Win, h2, Win, nullptr, binp, qkv, BB * TT, 3 * HH, HH, HH, 0);

    attn_last_kernel<<<16, 256>>>(qkv, olast);                            // 20
    head_kernel<<<BB, HH>>>(olast, Wout, bout, hW1, hb1, hW2, hb2, pred); // 21
}

// round 8
// speedup vs baseline: 1.7621x; 1.2680x over previous
#include <cuda_runtime.h>
#include <cuda_bf16.h>
#include <math.h>
#include <stdint.h>

// Problem constants
#define NND 50000
#define FF  256
#define HH  128
#define EE  800000
#define BB  64
#define TT  50

// ---------------- device scratch ----------------
__device__ float g_reduced[NND * HH];
__device__ float g_agg[NND * HH];
__device__ float g_s[NND * HH];
__device__ float g_invdeg[NND];
__device__ int   g_deg[NND];
__device__ float g_ts[BB * TT * HH];
__device__ float g_gates[BB * TT * 4 * HH];
__device__ float g_h1[BB * TT * HH];
__device__ float g_h2[BB * TT * HH];
__device__ float g_qkv[BB * TT * 3 * HH];
__device__ float g_olast[BB * HH];
__device__ float g_bias0[4 * HH];
__device__ float g_bias1[4 * HH];
__device__ float g_WhhT0[HH * 4 * HH];   // [128][512] transposed Whh0
__device__ float g_WhhT1[HH * 4 * HH];   // [128][512] transposed Whh1

__device__ __forceinline__ float sigf(float x) { return 1.0f / (1.0f + __expf(-x)); }
// tanh(x) = 1 - 2/(exp(2x)+1)  -> MUFU.EX2 + MUFU.RCP, same accuracy family as __expf
__device__ __forceinline__ float tanh_e(float x) { return 1.0f - 2.0f / (__expf(2.0f * x) + 1.0f); }

__device__ __forceinline__ uint32_t f2tf32(float f) {
    uint32_t u;
    asm("cvt.rna.tf32.f32 %0, %1;" : "=r"(u) : "f"(f));
    return u;
}

__device__ __forceinline__ void mma_tf32(float* d, const uint32_t* a, const uint32_t* b) {
    asm volatile("mma.sync.aligned.m16n8k8.row.col.f32.tf32.tf32.f32 "
                 "{%0,%1,%2,%3}, {%4,%5,%6,%7}, {%8,%9}, {%0,%1,%2,%3};"
                 : "+f"(d[0]), "+f"(d[1]), "+f"(d[2]), "+f"(d[3])
                 : "r"(a[0]), "r"(a[1]), "r"(a[2]), "r"(a[3]), "r"(b[0]), "r"(b[1]));
}

// ---------------- degree kernels ----------------
__global__ __launch_bounds__(256) void deg_kernel(const int* __restrict__ dst, int* __restrict__ deg, int E) {
    int i = blockIdx.x * blockDim.x + threadIdx.x;
    if (i < E) atomicAdd(&deg[dst[i]], 1);
}

__global__ __launch_bounds__(256) void invdeg_kernel(const int* __restrict__ deg, float* __restrict__ inv, int n) {
    int i = blockIdx.x * blockDim.x + threadIdx.x;
    if (i < n) inv[i] = 1.0f / (float)max(deg[i], 1);
}

// ---------------- weight transpose: Whh[512][128] -> WhhT[128][512] ----------------
__global__ __launch_bounds__(256) void transposeW_kernel(const float* __restrict__ W0,
                                                         const float* __restrict__ W1,
                                                         float* __restrict__ T0,
                                                         float* __restrict__ T1) {
    int idx = blockIdx.x * blockDim.x + threadIdx.x;
    if (idx < 512 * 128) {
        int j = idx >> 7;      // gate row 0..511
        int k = idx & 127;     // hidden col 0..127
        T0[k * 512 + j] = W0[idx];
        T1[k * 512 + j] = W1[idx];
    }
}

// ---------------- scatter-add (one warp per edge, v4 reductions) ----------------
__global__ __launch_bounds__(256) void scatter_add_kernel(const float* __restrict__ feat,
                                   const int* __restrict__ src,
                                   const int* __restrict__ dst,
                                   float* __restrict__ agg, int E) {
    int idx = blockIdx.x * blockDim.x + threadIdx.x;
    int e = idx >> 5;
    if (e >= E) return;
    int lane = idx & 31;
    int s = __ldg(src + e);
    int d = __ldg(dst + e);
    float4 v = *(const float4*)(feat + (size_t)s * HH + lane * 4);
    float* p = agg + (size_t)d * HH + lane * 4;
    asm volatile("red.global.add.v4.f32 [%0], {%1,%2,%3,%4};"
                 :: "l"(p), "f"(v.x), "f"(v.y), "f"(v.z), "f"(v.w) : "memory");
}

// ---------------- tf32 tensor-core NT GEMM ----------------
#define KT 16
__global__ __launch_bounds__(256) void gemm_tf32_kernel(
        const float* __restrict__ A1, const float* __restrict__ B1,
        const float* __restrict__ A2, const float* __restrict__ B2,
        const float* __restrict__ rowscale,
        const float* __restrict__ bias,
        float* __restrict__ C,
        int M, int N, int Ktot, int Ksplit, int relu) {
    __shared__ uint32_t As[2][KT][136];
    __shared__ uint32_t Bs[2][KT][136];
    const int tid  = threadIdx.x;
    const int m0   = blockIdx.x * 128;
    const int n0   = blockIdx.y * 128;
    const int warp = tid >> 5, lane = tid & 31;
    const int wm   = (warp >> 1) * 32;   // 4 warps in m
    const int wn   = (warp & 1) * 64;    // 2 warps in n
    const int g    = lane >> 2, c = lane & 3;
    const bool haveScale = (rowscale != nullptr);

    float acc[2][8][4];
#pragma unroll
    for (int mt = 0; mt < 2; mt++)
#pragma unroll
        for (int nt = 0; nt < 8; nt++)
#pragma unroll
            for (int r = 0; r < 4; r++) acc[mt][nt][r] = 0.0f;

    const int numSlabs = Ktot / KT;

    const int row0 = tid & 127, kc0 = tid >> 7;          // kc0 in {0,1}
    const int row1 = tid & 127, kc1 = (tid >> 7) + 2;    // {2,3}

    float4 pa[2], pb[2];

    auto loadSlab = [&](int s) {
        int kbase = s * KT;
        const float* A; const float* Bm; int lda, koff; bool sc;
        if (kbase < Ksplit) { A = A1; Bm = B1; lda = Ksplit;        koff = kbase;          sc = haveScale; }
        else                { A = A2; Bm = B2; lda = Ktot - Ksplit; koff = kbase - Ksplit; sc = false; }
        {
            int m = m0 + row0;
            pa[0] = make_float4(0.f, 0.f, 0.f, 0.f);
            if (m < M) {
                pa[0] = *(const float4*)(A + (size_t)m * lda + koff + kc0 * 4);
                if (sc) { float sv = rowscale[m]; pa[0].x *= sv; pa[0].y *= sv; pa[0].z *= sv; pa[0].w *= sv; }
            }
            pb[0] = *(const float4*)(Bm + (size_t)(n0 + row0) * lda + koff + kc0 * 4);
        }
        {
            int m = m0 + row1;
            pa[1] = make_float4(0.f, 0.f, 0.f, 0.f);
            if (m < M) {
                pa[1] = *(const float4*)(A + (size_t)m * lda + koff + kc1 * 4);
                if (sc) { float sv = rowscale[m]; pa[1].x *= sv; pa[1].y *= sv; pa[1].z *= sv; pa[1].w *= sv; }
            }
            pb[1] = *(const float4*)(Bm + (size_t)(n0 + row1) * lda + koff + kc1 * 4);
        }
    };

    auto storeSlab = [&](int buf) {
        int k0 = kc0 * 4;
        As[buf][k0 + 0][row0] = f2tf32(pa[0].x); As[buf][k0 + 1][row0] = f2tf32(pa[0].y);
        As[buf][k0 + 2][row0] = f2tf32(pa[0].z); As[buf][k0 + 3][row0] = f2tf32(pa[0].w);
        Bs[buf][k0 + 0][row0] = f2tf32(pb[0].x); Bs[buf][k0 + 1][row0] = f2tf32(pb[0].y);
        Bs[buf][k0 + 2][row0] = f2tf32(pb[0].z); Bs[buf][k0 + 3][row0] = f2tf32(pb[0].w);
        int k1 = kc1 * 4;
        As[buf][k1 + 0][row1] = f2tf32(pa[1].x); As[buf][k1 + 1][row1] = f2tf32(pa[1].y);
        As[buf][k1 + 2][row1] = f2tf32(pa[1].z); As[buf][k1 + 3][row1] = f2tf32(pa[1].w);
        Bs[buf][k1 + 0][row1] = f2tf32(pb[1].x); Bs[buf][k1 + 1][row1] = f2tf32(pb[1].y);
        Bs[buf][k1 + 2][row1] = f2tf32(pb[1].z); Bs[buf][k1 + 3][row1] = f2tf32(pb[1].w);
    };

    loadSlab(0);
    storeSlab(0);
    __syncthreads();

    for (int s = 0; s < numSlabs; s++) {
        int buf = s & 1;
        bool more = (s + 1) < numSlabs;
        if (more) loadSlab(s + 1);
#pragma unroll
        for (int k8 = 0; k8 < 2; k8++) {
            int kb = k8 * 8;
            uint32_t afr[2][4], bfr[8][2];
#pragma unroll
            for (int mt = 0; mt < 2; mt++) {
                int mb = wm + mt * 16 + g;
                afr[mt][0] = As[buf][kb + c][mb];
                afr[mt][1] = As[buf][kb + c][mb + 8];
                afr[mt][2] = As[buf][kb + c + 4][mb];
                afr[mt][3] = As[buf][kb + c + 4][mb + 8];
            }
#pragma unroll
            for (int nt = 0; nt < 8; nt++) {
                int nb = wn + nt * 8 + g;
                bfr[nt][0] = Bs[buf][kb + c][nb];
                bfr[nt][1] = Bs[buf][kb + c + 4][nb];
            }
#pragma unroll
            for (int mt = 0; mt < 2; mt++)
#pragma unroll
                for (int nt = 0; nt < 8; nt++)
                    mma_tf32(acc[mt][nt], afr[mt], bfr[nt]);
        }
        __syncthreads();
        if (more) {
            storeSlab(1 - buf);
            __syncthreads();
        }
    }

    // epilogue
#pragma unroll
    for (int mt = 0; mt < 2; mt++) {
#pragma unroll
        for (int nt = 0; nt < 8; nt++) {
            const float* d = acc[mt][nt];
            int mrow = m0 + wm + mt * 16 + g;
            int ncol = n0 + wn + nt * 8 + 2 * c;
            float b0v = 0.f, b1v = 0.f;
            if (bias) { b0v = bias[ncol]; b1v = bias[ncol + 1]; }
            float v0 = d[0] + b0v, v1 = d[1] + b1v;
            float v2 = d[2] + b0v, v3 = d[3] + b1v;
            if (relu) {
                v0 = fmaxf(v0, 0.f); v1 = fmaxf(v1, 0.f);
                v2 = fmaxf(v2, 0.f); v3 = fmaxf(v3, 0.f);
            }
            if (mrow < M)     *(float2*)(C + (size_t)mrow * N + ncol)       = make_float2(v0, v1);
            if (mrow + 8 < M) *(float2*)(C + (size_t)(mrow + 8) * N + ncol) = make_float2(v2, v3);
        }
    }
}

// ---------------- bias combine ----------------
__global__ __launch_bounds__(256) void bias2_kernel(const float* a, const float* b, float* o, int n) {
    int i = blockIdx.x * blockDim.x + threadIdx.x;
    if (i < n) o[i] = a[i] + b[i];
}

// ---------------- LSTM recurrence: 1 batch/CTA, 64 CTAs, 256 threads ----------------
// Thread j owns gates 2j, 2j+1 (float2 coalesced weight loads, MLP=16 prefetch).
// Activations use __expf-based sigmoid/tanh (MUFU EX2+RCP, no libm tanhf).
__global__ __launch_bounds__(256) void lstm_rec_kernel(
                                const float* __restrict__ gx,    // B*T*512, x@Wih^T + bih + bhh
                                const float* __restrict__ WhhT,  // [128][512]
                                float* __restrict__ hout) {      // B*T*128
    int b = blockIdx.x;       // 0..63
    int j = threadIdx.x;      // 0..255
    __shared__ float sh_h[HH];
    __shared__ float sh_g[4 * HH];
    float cstate = 0.0f;
    if (j < HH) sh_h[j] = 0.0f;
    __syncthreads();
    const float2* __restrict__ WT2 = (const float2*)WhhT;  // [k][256 float2]
    const float* gbase = gx + (size_t)b * TT * 512;
    for (int t = 0; t < TT; t++) {
        float2 g2 = *(const float2*)(gbase + t * 512 + 2 * j);
        float a0 = g2.x, a1 = g2.y;
#pragma unroll
        for (int kc = 0; kc < HH; kc += 16) {
            float2 w[16];
#pragma unroll
            for (int i = 0; i < 16; i++)
                w[i] = __ldg(&WT2[(kc + i) * 256 + j]);
#pragma unroll
            for (int i = 0; i < 16; i++) {
                float h = sh_h[kc + i];
                a0 += w[i].x * h;
                a1 += w[i].y * h;
            }
        }
        *(float2*)&sh_g[2 * j] = make_float2(a0, a1);
        __syncthreads();
        if (j < HH) {
            float gi = sh_g[j], gf = sh_g[HH + j], gg = sh_g[2 * HH + j], go = sh_g[3 * HH + j];
            cstate = sigf(gf) * cstate + sigf(gi) * tanh_e(gg);
            float h = sigf(go) * tanh_e(cstate);
            sh_h[j] = h;
            hout[((size_t)b * TT + t) * HH + j] = h;
        }
        __syncthreads();
    }
}

// ---------------- attention: only last query row needed ----------------
__global__ __launch_bounds__(256) void attn_last_kernel(const float* __restrict__ qkv, float* __restrict__ olast) {
    int gidx = blockIdx.x * blockDim.x + threadIdx.x;
    int w = gidx >> 5;                // 0..127 : (b, head)
    if (w >= BB * 2) return;
    int lane = threadIdx.x & 31;
    int wl = threadIdx.x >> 5;
    int b = w >> 1, h = w & 1;
    const float* base = qkv + (size_t)b * TT * 384;
    const float* q = base + 49 * 384 + h * 64;
    float q0 = q[lane], q1 = q[lane + 32];
    __shared__ float sc[8][TT];
    for (int j = 0; j < TT; j++) {
        const float* kp = base + j * 384 + 128 + h * 64;
        float p = q0 * kp[lane] + q1 * kp[lane + 32];
#pragma unroll
        for (int o = 16; o; o >>= 1) p += __shfl_down_sync(0xffffffffu, p, o);
        if (lane == 0) sc[wl][j] = p * 0.125f;   // /sqrt(64)
    }
    __syncwarp();
    float v0 = (lane < TT) ? sc[wl][lane] : -1e30f;
    float v1 = (lane + 32 < TT) ? sc[wl][lane + 32] : -1e30f;
    float mx = fmaxf(v0, v1);
#pragma unroll
    for (int o = 16; o; o >>= 1) mx = fmaxf(mx, __shfl_xor_sync(0xffffffffu, mx, o));
    float e0 = (lane < TT) ? expf(v0 - mx) : 0.f;
    float e1 = (lane + 32 < TT) ? expf(v1 - mx) : 0.f;
    float s = e0 + e1;
#pragma unroll
    for (int o = 16; o; o >>= 1) s += __shfl_xor_sync(0xffffffffu, s, o);
    float inv = 1.0f / s;
    if (lane < TT) sc[wl][lane] = e0 * inv;
    if (lane + 32 < TT) sc[wl][lane + 32] = e1 * inv;
    __syncwarp();
    float a0 = 0.f, a1 = 0.f;
    for (int j = 0; j < TT; j++) {
        float wj = sc[wl][j];
        const float* vp = base + j * 384 + 256 + h * 64;
        a0 += wj * vp[lane];
        a1 += wj * vp[lane + 32];
    }
    olast[b * HH + h * 64 + lane] = a0;
    olast[b * HH + h * 64 + lane + 32] = a1;
}

// ---------------- final: out-proj (last row) + MLP head ----------------
__global__ __launch_bounds__(128) void head_kernel(const float* __restrict__ olast,
                            const float* __restrict__ Wout, const float* __restrict__ bout,
                            const float* __restrict__ W1, const float* __restrict__ b1,
                            const float* __restrict__ W2, const float* __restrict__ b2,
                            float* __restrict__ pred) {
    int b = blockIdx.x;
    int j = threadIdx.x;  // 128
    __shared__ float o[HH], a[HH], hid[64];
    o[j] = olast[b * HH + j];
    __syncthreads();
    {
        float acc = bout[j];
        const float* w = Wout + (size_t)j * HH;
#pragma unroll 4
        for (int k = 0; k < HH; k++) acc += o[k] * w[k];
        a[j] = acc;
    }
    __syncthreads();
    if (j < 64) {
        float acc = b1[j];
        const float* w = W1 + (size_t)j * HH;
#pragma unroll 4
        for (int k = 0; k < HH; k++) acc += a[k] * w[k];
        hid[j] = fmaxf(acc, 0.0f);
    }
    __syncthreads();
    if (j == 0) {
        float p = b2[0];
#pragma unroll
        for (int k = 0; k < 64; k++) p += hid[k] * W2[k];
        pred[b] = p;
    }
}

// ---------------- host launch ----------------
extern "C" void kernel_launch(void* const* d_in, const int* in_sizes, int n_in,
                              void* d_out, int out_size) {
    (void)in_sizes; (void)n_in; (void)out_size;
    const float* x     = (const float*)d_in[0];
    const int*   eidx  = (const int*)d_in[1];
    const float* tseq  = (const float*)d_in[2];
    const float* W_red = (const float*)d_in[3];
    const float* b_red = (const float*)d_in[4];
    const float* s1Wl  = (const float*)d_in[5];
    const float* s1bl  = (const float*)d_in[6];
    const float* s1Wr  = (const float*)d_in[7];
    const float* s2Wl  = (const float*)d_in[8];
    const float* s2bl  = (const float*)d_in[9];
    const float* s2Wr  = (const float*)d_in[10];
    const float* Wih0  = (const float*)d_in[11];
    const float* Whh0  = (const float*)d_in[12];
    const float* bih0  = (const float*)d_in[13];
    const float* bhh0  = (const float*)d_in[14];
    const float* Wih1  = (const float*)d_in[15];
    const float* Whh1  = (const float*)d_in[16];
    const float* bih1  = (const float*)d_in[17];
    const float* bhh1  = (const float*)d_in[18];
    const float* Win   = (const float*)d_in[19];
    const float* binp  = (const float*)d_in[20];
    const float* Wout  = (const float*)d_in[21];
    const float* bout  = (const float*)d_in[22];
    const float* hW1   = (const float*)d_in[23];
    const float* hb1   = (const float*)d_in[24];
    const float* hW2   = (const float*)d_in[25];
    const float* hb2   = (const float*)d_in[26];

    float* out     = (float*)d_out;
    float* pred    = out;        // (64,1)
    float* spatial = out + BB;   // (50000,128)

    const int* src = eidx;
    const int* dst = eidx + EE;

    void* p;
    cudaGetSymbolAddress(&p, g_reduced); float* reduced = (float*)p;
    cudaGetSymbolAddress(&p, g_agg);     float* agg     = (float*)p;
    cudaGetSymbolAddress(&p, g_s);       float* sbuf    = (float*)p;
    cudaGetSymbolAddress(&p, g_invdeg);  float* invdeg  = (float*)p;
    cudaGetSymbolAddress(&p, g_deg);     int*   deg     = (int*)p;
    cudaGetSymbolAddress(&p, g_ts);      float* ts      = (float*)p;
    cudaGetSymbolAddress(&p, g_gates);   float* gates   = (float*)p;
    cudaGetSymbolAddress(&p, g_h1);      float* h1      = (float*)p;
    cudaGetSymbolAddress(&p, g_h2);      float* h2      = (float*)p;
    cudaGetSymbolAddress(&p, g_qkv);     float* qkv     = (float*)p;
    cudaGetSymbolAddress(&p, g_olast);   float* olast   = (float*)p;
    cudaGetSymbolAddress(&p, g_bias0);   float* bias0   = (float*)p;
    cudaGetSymbolAddress(&p, g_bias1);   float* bias1   = (float*)p;
    cudaGetSymbolAddress(&p, g_WhhT0);   float* WhhT0   = (float*)p;
    cudaGetSymbolAddress(&p, g_WhhT1);   float* WhhT1   = (float*)p;

    // kernel launch order (memsets excluded from ncu count last time was ambiguous;
    // lstm0 sits at kernel positions 5 AND the slot after is cheap, so either
    // off-by-one interpretation still lands on or near lstm0).
    transposeW_kernel<<<256, 256>>>(Whh0, Whh1, WhhT0, WhhT1);            // k1
    bias2_kernel<<<2, 256>>>(bih0, bhh0, bias0, 4 * HH);                  // k2
    // k3: ts = time_sequence @ W_red^T + b_red   (3200 x 128)
    gemm_tf32_kernel<<<dim3((BB * TT + 127) / 128, HH / 128), 256>>>(
        tseq, W_red, tseq, W_red, nullptr, b_red, ts, BB * TT, HH, FF, FF, 0);
    // k4: gates0 = ts @ Wih0^T + (bih0+bhh0)
    gemm_tf32_kernel<<<dim3((BB * TT + 127) / 128, (4 * HH) / 128), 256>>>(
        ts, Wih0, ts, Wih0, nullptr, bias0, gates, BB * TT, 4 * HH, HH, HH, 0);
    // k5: LSTM layer 0   <-- profile target
    lstm_rec_kernel<<<BB, 256>>>(gates, WhhT0, h1);
    // k6
    bias2_kernel<<<2, 256>>>(bih1, bhh1, bias1, 4 * HH);

    cudaMemsetAsync(agg, 0, sizeof(float) * (size_t)NND * HH);
    cudaMemsetAsync(deg, 0, sizeof(int) * NND);
    deg_kernel<<<(EE + 255) / 256, 256>>>(dst, deg, EE);
    invdeg_kernel<<<(NND + 255) / 256, 256>>>(deg, invdeg, NND);

    // reduced = x @ W_red^T + b_red
    gemm_tf32_kernel<<<dim3((NND + 127) / 128, HH / 128), 256>>>(
        x, W_red, x, W_red, nullptr, b_red, reduced, NND, HH, FF, FF, 0);

    // agg += reduced[src] scattered to dst
    {
        long long tot = (long long)EE * 32;
        scatter_add_kernel<<<(unsigned)((tot + 255) / 256), 256>>>(reduced, src, dst, agg, EE);
    }

    // s = relu((agg*invdeg) @ Wl1^T + bl1 + reduced @ Wr1^T)
    gemm_tf32_kernel<<<dim3((NND + 127) / 128, HH / 128), 256>>>(
        agg, s1Wl, reduced, s1Wr, invdeg, s1bl, sbuf, NND, HH, 2 * HH, HH, 1);

    cudaMemsetAsync(agg, 0, sizeof(float) * (size_t)NND * HH);
    {
        long long tot = (long long)EE * 32;
        scatter_add_kernel<<<(unsigned)((tot + 255) / 256), 256>>>(sbuf, src, dst, agg, EE);
    }
    // spatial = relu((agg*invdeg) @ Wl2^T + bl2 + s @ Wr2^T)
    gemm_tf32_kernel<<<dim3((NND + 127) / 128, HH / 128), 256>>>(
        agg, s2Wl, sbuf, s2Wr, invdeg, s2bl, spatial, NND, HH, 2 * HH, HH, 1);

    // gates1 = h1 @ Wih1^T + (bih1+bhh1)
    gemm_tf32_kernel<<<dim3((BB * TT + 127) / 128, (4 * HH) / 128), 256>>>(
        h1, Wih1, h1, Wih1, nullptr, bias1, gates, BB * TT, 4 * HH, HH, HH, 0);
    lstm_rec_kernel<<<BB, 256>>>(gates, WhhT1, h2);

    // qkv = h2 @ Win^T + bin   (3200 x 384)
    gemm_tf32_kernel<<<dim3((BB * TT + 127) / 128, (3 * HH) / 128), 256>>>(
        h2, Win, h2, Win, nullptr, binp, qkv, BB * TT, 3 * HH, HH, HH, 0);

    attn_last_kernel<<<16, 256>>>(qkv, olast);
    head_kernel<<<BB, HH>>>(olast, Wout, bout, hW1, hb1, hW2, hb2, pred);
}

// round 9
// speedup vs baseline: 2.4102x; 1.3678x over previous
#include <cuda_runtime.h>
#include <cuda_bf16.h>
#include <math.h>
#include <stdint.h>

// Problem constants
#define NND 50000
#define FF  256
#define HH  128
#define EE  800000
#define BB  64
#define TT  50

// ---------------- device scratch ----------------
__device__ float g_reduced[NND * HH];
__device__ float g_agg[NND * HH];
__device__ float g_s[NND * HH];
__device__ float g_invdeg[NND];
__device__ int   g_deg[NND];
__device__ float g_ts[BB * TT * HH];
__device__ float g_gates[BB * TT * 4 * HH];
__device__ float g_h1[BB * TT * HH];
__device__ float g_h2[BB * TT * HH];
__device__ float g_qkv[BB * TT * 3 * HH];
__device__ float g_olast[BB * HH];
__device__ __nv_bfloat16 g_WhhTb0[HH * 4 * HH];   // [128][512] transposed bf16 Whh0
__device__ __nv_bfloat16 g_WhhTb1[HH * 4 * HH];   // [128][512] transposed bf16 Whh1

__device__ __forceinline__ float sigf(float x) { return 1.0f / (1.0f + __expf(-x)); }
// tanh(x) = 1 - 2/(exp(2x)+1)  -> MUFU.EX2 + MUFU.RCP
__device__ __forceinline__ float tanh_e(float x) { return 1.0f - 2.0f / (__expf(2.0f * x) + 1.0f); }

__device__ __forceinline__ uint32_t f2tf32(float f) {
    uint32_t u;
    asm("cvt.rna.tf32.f32 %0, %1;" : "=r"(u) : "f"(f));
    return u;
}

__device__ __forceinline__ void mma_tf32(float* d, const uint32_t* a, const uint32_t* b) {
    asm volatile("mma.sync.aligned.m16n8k8.row.col.f32.tf32.tf32.f32 "
                 "{%0,%1,%2,%3}, {%4,%5,%6,%7}, {%8,%9}, {%0,%1,%2,%3};"
                 : "+f"(d[0]), "+f"(d[1]), "+f"(d[2]), "+f"(d[3])
                 : "r"(a[0]), "r"(a[1]), "r"(a[2]), "r"(a[3]), "r"(b[0]), "r"(b[1]));
}

// ---------------- degree kernels ----------------
__global__ __launch_bounds__(256) void deg_kernel(const int* __restrict__ dst, int* __restrict__ deg, int E) {
    int i = blockIdx.x * blockDim.x + threadIdx.x;
    if (i < E) atomicAdd(&deg[dst[i]], 1);
}

__global__ __launch_bounds__(256) void invdeg_kernel(const int* __restrict__ deg, float* __restrict__ inv, int n) {
    int i = blockIdx.x * blockDim.x + threadIdx.x;
    if (i < n) inv[i] = 1.0f / (float)max(deg[i], 1);
}

// ---------------- weight transpose+convert: Whh[512][128] f32 -> WhhT[128][512] bf16 ----
__global__ __launch_bounds__(256) void transposeW_kernel(const float* __restrict__ W0,
                                                         const float* __restrict__ W1,
                                                         __nv_bfloat16* __restrict__ T0,
                                                         __nv_bfloat16* __restrict__ T1) {
    int idx = blockIdx.x * blockDim.x + threadIdx.x;
    if (idx < 512 * 128) {
        int j = idx >> 7;      // gate row 0..511
        int k = idx & 127;     // hidden col 0..127
        T0[k * 512 + j] = __float2bfloat16(W0[idx]);
        T1[k * 512 + j] = __float2bfloat16(W1[idx]);
    }
}

// ---------------- scatter-add (one warp per edge, v4 reductions) ----------------
__global__ __launch_bounds__(256) void scatter_add_kernel(const float* __restrict__ feat,
                                   const int* __restrict__ src,
                                   const int* __restrict__ dst,
                                   float* __restrict__ agg, int E) {
    int idx = blockIdx.x * blockDim.x + threadIdx.x;
    int e = idx >> 5;
    if (e >= E) return;
    int lane = idx & 31;
    int s = __ldg(src + e);
    int d = __ldg(dst + e);
    float4 v = *(const float4*)(feat + (size_t)s * HH + lane * 4);
    float* p = agg + (size_t)d * HH + lane * 4;
    asm volatile("red.global.add.v4.f32 [%0], {%1,%2,%3,%4};"
                 :: "l"(p), "f"(v.x), "f"(v.y), "f"(v.z), "f"(v.w) : "memory");
}

// ---------------- tf32 tensor-core NT GEMM ----------------
#define KT 16
__global__ __launch_bounds__(256) void gemm_tf32_kernel(
        const float* __restrict__ A1, const float* __restrict__ B1,
        const float* __restrict__ A2, const float* __restrict__ B2,
        const float* __restrict__ rowscale,
        const float* __restrict__ bias,
        float* __restrict__ C,
        int M, int N, int Ktot, int Ksplit, int relu) {
    __shared__ uint32_t As[2][KT][136];
    __shared__ uint32_t Bs[2][KT][136];
    const int tid  = threadIdx.x;
    const int m0   = blockIdx.x * 128;
    const int n0   = blockIdx.y * 128;
    const int warp = tid >> 5, lane = tid & 31;
    const int wm   = (warp >> 1) * 32;   // 4 warps in m
    const int wn   = (warp & 1) * 64;    // 2 warps in n
    const int g    = lane >> 2, c = lane & 3;
    const bool haveScale = (rowscale != nullptr);

    float acc[2][8][4];
#pragma unroll
    for (int mt = 0; mt < 2; mt++)
#pragma unroll
        for (int nt = 0; nt < 8; nt++)
#pragma unroll
            for (int r = 0; r < 4; r++) acc[mt][nt][r] = 0.0f;

    const int numSlabs = Ktot / KT;

    const int row0 = tid & 127, kc0 = tid >> 7;          // kc0 in {0,1}
    const int row1 = tid & 127, kc1 = (tid >> 7) + 2;    // {2,3}

    float4 pa[2], pb[2];

    auto loadSlab = [&](int s) {
        int kbase = s * KT;
        const float* A; const float* Bm; int lda, koff; bool sc;
        if (kbase < Ksplit) { A = A1; Bm = B1; lda = Ksplit;        koff = kbase;          sc = haveScale; }
        else                { A = A2; Bm = B2; lda = Ktot - Ksplit; koff = kbase - Ksplit; sc = false; }
        {
            int m = m0 + row0;
            pa[0] = make_float4(0.f, 0.f, 0.f, 0.f);
            if (m < M) {
                pa[0] = *(const float4*)(A + (size_t)m * lda + koff + kc0 * 4);
                if (sc) { float sv = rowscale[m]; pa[0].x *= sv; pa[0].y *= sv; pa[0].z *= sv; pa[0].w *= sv; }
            }
            pb[0] = *(const float4*)(Bm + (size_t)(n0 + row0) * lda + koff + kc0 * 4);
        }
        {
            int m = m0 + row1;
            pa[1] = make_float4(0.f, 0.f, 0.f, 0.f);
            if (m < M) {
                pa[1] = *(const float4*)(A + (size_t)m * lda + koff + kc1 * 4);
                if (sc) { float sv = rowscale[m]; pa[1].x *= sv; pa[1].y *= sv; pa[1].z *= sv; pa[1].w *= sv; }
            }
            pb[1] = *(const float4*)(Bm + (size_t)(n0 + row1) * lda + koff + kc1 * 4);
        }
    };

    auto storeSlab = [&](int buf) {
        int k0 = kc0 * 4;
        As[buf][k0 + 0][row0] = f2tf32(pa[0].x); As[buf][k0 + 1][row0] = f2tf32(pa[0].y);
        As[buf][k0 + 2][row0] = f2tf32(pa[0].z); As[buf][k0 + 3][row0] = f2tf32(pa[0].w);
        Bs[buf][k0 + 0][row0] = f2tf32(pb[0].x); Bs[buf][k0 + 1][row0] = f2tf32(pb[0].y);
        Bs[buf][k0 + 2][row0] = f2tf32(pb[0].z); Bs[buf][k0 + 3][row0] = f2tf32(pb[0].w);
        int k1 = kc1 * 4;
        As[buf][k1 + 0][row1] = f2tf32(pa[1].x); As[buf][k1 + 1][row1] = f2tf32(pa[1].y);
        As[buf][k1 + 2][row1] = f2tf32(pa[1].z); As[buf][k1 + 3][row1] = f2tf32(pa[1].w);
        Bs[buf][k1 + 0][row1] = f2tf32(pb[1].x); Bs[buf][k1 + 1][row1] = f2tf32(pb[1].y);
        Bs[buf][k1 + 2][row1] = f2tf32(pb[1].z); Bs[buf][k1 + 3][row1] = f2tf32(pb[1].w);
    };

    loadSlab(0);
    storeSlab(0);
    __syncthreads();

    for (int s = 0; s < numSlabs; s++) {
        int buf = s & 1;
        bool more = (s + 1) < numSlabs;
        if (more) loadSlab(s + 1);
#pragma unroll
        for (int k8 = 0; k8 < 2; k8++) {
            int kb = k8 * 8;
            uint32_t afr[2][4], bfr[8][2];
#pragma unroll
            for (int mt = 0; mt < 2; mt++) {
                int mb = wm + mt * 16 + g;
                afr[mt][0] = As[buf][kb + c][mb];
                afr[mt][1] = As[buf][kb + c][mb + 8];
                afr[mt][2] = As[buf][kb + c + 4][mb];
                afr[mt][3] = As[buf][kb + c + 4][mb + 8];
            }
#pragma unroll
            for (int nt = 0; nt < 8; nt++) {
                int nb = wn + nt * 8 + g;
                bfr[nt][0] = Bs[buf][kb + c][nb];
                bfr[nt][1] = Bs[buf][kb + c + 4][nb];
            }
#pragma unroll
            for (int mt = 0; mt < 2; mt++)
#pragma unroll
                for (int nt = 0; nt < 8; nt++)
                    mma_tf32(acc[mt][nt], afr[mt], bfr[nt]);
        }
        __syncthreads();
        if (more) {
            storeSlab(1 - buf);
            __syncthreads();
        }
    }

    // epilogue
#pragma unroll
    for (int mt = 0; mt < 2; mt++) {
#pragma unroll
        for (int nt = 0; nt < 8; nt++) {
            const float* d = acc[mt][nt];
            int mrow = m0 + wm + mt * 16 + g;
            int ncol = n0 + wn + nt * 8 + 2 * c;
            float b0v = 0.f, b1v = 0.f;
            if (bias) { b0v = bias[ncol]; b1v = bias[ncol + 1]; }
            float v0 = d[0] + b0v, v1 = d[1] + b1v;
            float v2 = d[2] + b0v, v3 = d[3] + b1v;
            if (relu) {
                v0 = fmaxf(v0, 0.f); v1 = fmaxf(v1, 0.f);
                v2 = fmaxf(v2, 0.f); v3 = fmaxf(v3, 0.f);
            }
            if (mrow < M)     *(float2*)(C + (size_t)mrow * N + ncol)       = make_float2(v0, v1);
            if (mrow + 8 < M) *(float2*)(C + (size_t)(mrow + 8) * N + ncol) = make_float2(v2, v3);
        }
    }
}

// ---------------- LSTM recurrence: smem-resident bf16 weights ----------------
// 64 CTAs (1 batch each), 256 threads. Thread j owns gates 2j, 2j+1.
// Weights (128KB bf16) loaded into smem ONCE, reused for all 50 steps.
// gx = x@Wih^T + bih (from GEMM); bhh added here.
#define LSTM_SMEM (HH * 256 * 4 + HH * 4 + 4 * HH * 4)   // w(131072) + h(512) + g(2048)
__global__ __launch_bounds__(256) void lstm_rec_kernel(
                                const float* __restrict__ gx,
                                const __nv_bfloat162* __restrict__ Wbf,  // [128][256] bf16x2
                                const float* __restrict__ bhh,           // [512]
                                float* __restrict__ hout) {              // B*T*128
    extern __shared__ char smem[];
    __nv_bfloat162* sw = (__nv_bfloat162*)smem;               // [128*256]
    float* sh_h = (float*)(smem + HH * 256 * 4);              // [128]
    float* sh_g = (float*)(smem + HH * 256 * 4 + HH * 4);     // [512]
    const int b = blockIdx.x;
    const int j = threadIdx.x;   // 0..255

    // load weights once (coalesced: 128KB / 256 threads)
    for (int idx = j; idx < HH * 256; idx += 256) sw[idx] = Wbf[idx];
    const float2 bh2 = make_float2(__ldg(bhh + 2 * j), __ldg(bhh + 2 * j + 1));
    float cstate = 0.0f;
    if (j < HH) sh_h[j] = 0.0f;
    __syncthreads();

    const float* gbase = gx + (size_t)b * TT * 512;
    for (int t = 0; t < TT; t++) {
        float2 g2 = *(const float2*)(gbase + t * 512 + 2 * j);
        float a0 = g2.x + bh2.x, a1 = g2.y + bh2.y;
#pragma unroll 16
        for (int k = 0; k < HH; k++) {
            float2 w = __bfloat1622float2(sw[k * 256 + j]);
            float h = sh_h[k];
            a0 += w.x * h;
            a1 += w.y * h;
        }
        *(float2*)&sh_g[2 * j] = make_float2(a0, a1);
        __syncthreads();
        if (j < HH) {
            float gi = sh_g[j], gf = sh_g[HH + j], gg = sh_g[2 * HH + j], go = sh_g[3 * HH + j];
            cstate = sigf(gf) * cstate + sigf(gi) * tanh_e(gg);
            float h = sigf(go) * tanh_e(cstate);
            sh_h[j] = h;
            hout[((size_t)b * TT + t) * HH + j] = h;
        }
        __syncthreads();
    }
}

// ---------------- attention: only last query row needed ----------------
__global__ __launch_bounds__(256) void attn_last_kernel(const float* __restrict__ qkv, float* __restrict__ olast) {
    int gidx = blockIdx.x * blockDim.x + threadIdx.x;
    int w = gidx >> 5;                // 0..127 : (b, head)
    if (w >= BB * 2) return;
    int lane = threadIdx.x & 31;
    int wl = threadIdx.x >> 5;
    int b = w >> 1, h = w & 1;
    const float* base = qkv + (size_t)b * TT * 384;
    const float* q = base + 49 * 384 + h * 64;
    float q0 = q[lane], q1 = q[lane + 32];
    __shared__ float sc[8][TT];
    for (int j = 0; j < TT; j++) {
        const float* kp = base + j * 384 + 128 + h * 64;
        float p = q0 * kp[lane] + q1 * kp[lane + 32];
#pragma unroll
        for (int o = 16; o; o >>= 1) p += __shfl_down_sync(0xffffffffu, p, o);
        if (lane == 0) sc[wl][j] = p * 0.125f;   // /sqrt(64)
    }
    __syncwarp();
    float v0 = (lane < TT) ? sc[wl][lane] : -1e30f;
    float v1 = (lane + 32 < TT) ? sc[wl][lane + 32] : -1e30f;
    float mx = fmaxf(v0, v1);
#pragma unroll
    for (int o = 16; o; o >>= 1) mx = fmaxf(mx, __shfl_xor_sync(0xffffffffu, mx, o));
    float e0 = (lane < TT) ? expf(v0 - mx) : 0.f;
    float e1 = (lane + 32 < TT) ? expf(v1 - mx) : 0.f;
    float s = e0 + e1;
#pragma unroll
    for (int o = 16; o; o >>= 1) s += __shfl_xor_sync(0xffffffffu, s, o);
    float inv = 1.0f / s;
    if (lane < TT) sc[wl][lane] = e0 * inv;
    if (lane + 32 < TT) sc[wl][lane + 32] = e1 * inv;
    __syncwarp();
    float a0 = 0.f, a1 = 0.f;
    for (int j = 0; j < TT; j++) {
        float wj = sc[wl][j];
        const float* vp = base + j * 384 + 256 + h * 64;
        a0 += wj * vp[lane];
        a1 += wj * vp[lane + 32];
    }
    olast[b * HH + h * 64 + lane] = a0;
    olast[b * HH + h * 64 + lane + 32] = a1;
}

// ---------------- final: out-proj (last row) + MLP head ----------------
__global__ __launch_bounds__(128) void head_kernel(const float* __restrict__ olast,
                            const float* __restrict__ Wout, const float* __restrict__ bout,
                            const float* __restrict__ W1, const float* __restrict__ b1,
                            const float* __restrict__ W2, const float* __restrict__ b2,
                            float* __restrict__ pred) {
    int b = blockIdx.x;
    int j = threadIdx.x;  // 128
    __shared__ float o[HH], a[HH], hid[64];
    o[j] = olast[b * HH + j];
    __syncthreads();
    {
        float acc = bout[j];
        const float* w = Wout + (size_t)j * HH;
#pragma unroll 4
        for (int k = 0; k < HH; k++) acc += o[k] * w[k];
        a[j] = acc;
    }
    __syncthreads();
    if (j < 64) {
        float acc = b1[j];
        const float* w = W1 + (size_t)j * HH;
#pragma unroll 4
        for (int k = 0; k < HH; k++) acc += a[k] * w[k];
        hid[j] = fmaxf(acc, 0.0f);
    }
    __syncthreads();
    if (j == 0) {
        float p = b2[0];
#pragma unroll
        for (int k = 0; k < 64; k++) p += hid[k] * W2[k];
        pred[b] = p;
    }
}

// ---------------- host launch ----------------
extern "C" void kernel_launch(void* const* d_in, const int* in_sizes, int n_in,
                              void* d_out, int out_size) {
    (void)in_sizes; (void)n_in; (void)out_size;
    const float* x     = (const float*)d_in[0];
    const int*   eidx  = (const int*)d_in[1];
    const float* tseq  = (const float*)d_in[2];
    const float* W_red = (const float*)d_in[3];
    const float* b_red = (const float*)d_in[4];
    const float* s1Wl  = (const float*)d_in[5];
    const float* s1bl  = (const float*)d_in[6];
    const float* s1Wr  = (const float*)d_in[7];
    const float* s2Wl  = (const float*)d_in[8];
    const float* s2bl  = (const float*)d_in[9];
    const float* s2Wr  = (const float*)d_in[10];
    const float* Wih0  = (const float*)d_in[11];
    const float* Whh0  = (const float*)d_in[12];
    const float* bih0  = (const float*)d_in[13];
    const float* bhh0  = (const float*)d_in[14];
    const float* Wih1  = (const float*)d_in[15];
    const float* Whh1  = (const float*)d_in[16];
    const float* bih1  = (const float*)d_in[17];
    const float* bhh1  = (const float*)d_in[18];
    const float* Win   = (const float*)d_in[19];
    const float* binp  = (const float*)d_in[20];
    const float* Wout  = (const float*)d_in[21];
    const float* bout  = (const float*)d_in[22];
    const float* hW1   = (const float*)d_in[23];
    const float* hb1   = (const float*)d_in[24];
    const float* hW2   = (const float*)d_in[25];
    const float* hb2   = (const float*)d_in[26];

    float* out     = (float*)d_out;
    float* pred    = out;        // (64,1)
    float* spatial = out + BB;   // (50000,128)

    const int* src = eidx;
    const int* dst = eidx + EE;

    void* p;
    cudaGetSymbolAddress(&p, g_reduced); float* reduced = (float*)p;
    cudaGetSymbolAddress(&p, g_agg);     float* agg     = (float*)p;
    cudaGetSymbolAddress(&p, g_s);       float* sbuf    = (float*)p;
    cudaGetSymbolAddress(&p, g_invdeg);  float* invdeg  = (float*)p;
    cudaGetSymbolAddress(&p, g_deg);     int*   deg     = (int*)p;
    cudaGetSymbolAddress(&p, g_ts);      float* ts      = (float*)p;
    cudaGetSymbolAddress(&p, g_gates);   float* gates   = (float*)p;
    cudaGetSymbolAddress(&p, g_h1);      float* h1      = (float*)p;
    cudaGetSymbolAddress(&p, g_h2);      float* h2      = (float*)p;
    cudaGetSymbolAddress(&p, g_qkv);     float* qkv     = (float*)p;
    cudaGetSymbolAddress(&p, g_olast);   float* olast   = (float*)p;
    cudaGetSymbolAddress(&p, g_WhhTb0);  __nv_bfloat16* WhhTb0 = (__nv_bfloat16*)p;
    cudaGetSymbolAddress(&p, g_WhhTb1);  __nv_bfloat16* WhhTb1 = (__nv_bfloat16*)p;

    static bool attrSet = false;
    if (!attrSet) {
        cudaFuncSetAttribute(lstm_rec_kernel, cudaFuncAttributeMaxDynamicSharedMemorySize, LSTM_SMEM);
        attrSet = true;
    }

    // ---- kernel launch order (lstm0 is the 4th of ours = overall #6 => ncu target) ----
    transposeW_kernel<<<256, 256>>>(Whh0, Whh1, WhhTb0, WhhTb1);          // k1

    // k2: ts = time_sequence @ W_red^T + b_red   (3200 x 128)
    gemm_tf32_kernel<<<dim3((BB * TT + 127) / 128, HH / 128), 256>>>(
        tseq, W_red, tseq, W_red, nullptr, b_red, ts, BB * TT, HH, FF, FF, 0);

    // k3: gates0 = ts @ Wih0^T + bih0     (bhh0 added inside lstm)
    gemm_tf32_kernel<<<dim3((BB * TT + 127) / 128, (4 * HH) / 128), 256>>>(
        ts, Wih0, ts, Wih0, nullptr, bih0, gates, BB * TT, 4 * HH, HH, HH, 0);

    // k4: LSTM layer 0   <-- PROFILE TARGET
    lstm_rec_kernel<<<BB, 256, LSTM_SMEM>>>(gates, (const __nv_bfloat162*)WhhTb0, bhh0, h1);

    cudaMemsetAsync(agg, 0, sizeof(float) * (size_t)NND * HH);
    cudaMemsetAsync(deg, 0, sizeof(int) * NND);
    deg_kernel<<<(EE + 255) / 256, 256>>>(dst, deg, EE);
    invdeg_kernel<<<(NND + 255) / 256, 256>>>(deg, invdeg, NND);

    // reduced = x @ W_red^T + b_red
    gemm_tf32_kernel<<<dim3((NND + 127) / 128, HH / 128), 256>>>(
        x, W_red, x, W_red, nullptr, b_red, reduced, NND, HH, FF, FF, 0);

    // agg += reduced[src] scattered to dst
    {
        long long tot = (long long)EE * 32;
        scatter_add_kernel<<<(unsigned)((tot + 255) / 256), 256>>>(reduced, src, dst, agg, EE);
    }

    // s = relu((agg*invdeg) @ Wl1^T + bl1 + reduced @ Wr1^T)
    gemm_tf32_kernel<<<dim3((NND + 127) / 128, HH / 128), 256>>>(
        agg, s1Wl, reduced, s1Wr, invdeg, s1bl, sbuf, NND, HH, 2 * HH, HH, 1);

    cudaMemsetAsync(agg, 0, sizeof(float) * (size_t)NND * HH);
    {
        long long tot = (long long)EE * 32;
        scatter_add_kernel<<<(unsigned)((tot + 255) / 256), 256>>>(sbuf, src, dst, agg, EE);
    }
    // spatial = relu((agg*invdeg) @ Wl2^T + bl2 + s @ Wr2^T)
    gemm_tf32_kernel<<<dim3((NND + 127) / 128, HH / 128), 256>>>(
        agg, s2Wl, sbuf, s2Wr, invdeg, s2bl, spatial, NND, HH, 2 * HH, HH, 1);

    // gates1 = h1 @ Wih1^T + bih1
    gemm_tf32_kernel<<<dim3((BB * TT + 127) / 128, (4 * HH) / 128), 256>>>(
        h1, Wih1, h1, Wih1, nullptr, bih1, gates, BB * TT, 4 * HH, HH, HH, 0);
    lstm_rec_kernel<<<BB, 256, LSTM_SMEM>>>(gates, (const __nv_bfloat162*)WhhTb1, bhh1, h2);

    // qkv = h2 @ Win^T + bin   (3200 x 384)
    gemm_tf32_kernel<<<dim3((BB * TT + 127) / 128, (3 * HH) / 128), 256>>>(
        h2, Win, h2, Win, nullptr, binp, qkv, BB * TT, 3 * HH, HH, HH, 0);

    attn_last_kernel<<<16, 256>>>(qkv, olast);
    head_kernel<<<BB, HH>>>(olast, Wout, bout, hW1, hb1, hW2, hb2, pred);
}